// round 13
// baseline (speedup 1.0000x reference)
#include <cuda_runtime.h>
#include <cuda_fp16.h>
#include <math.h>
#include <stdint.h>

// ---------------- problem dims ----------------
#define BB   8
#define TT   512
#define CC   2048
#define HH   32
#define ZZ   64
#define AA   2048
#define MR   (BB*TT)         // 4096
#define TMX  32
#define TDX  64
#define NMIX 256
#define NTD  128
#define EPS_GN (1e-5f * 64.0f)

#define KDIM    2048
#define KCHUNKS 64           // K chunks of 32 (for K=2048 operands)
#define NST     3
#define PGRID   296

// ---------------- scratch ----------------
__device__ float g_shift[BB*CC];
__device__ float g_reset[BB];
__device__ int   g_ctr[8];
// A-side operands: fp16 hi/lo split, tiled A-layout
__device__ __align__(1024) __half g_xxx_hi[MR*CC];
__device__ __align__(1024) __half g_xxx_lo[MR*CC];
__device__ __align__(1024) __half g_act_hi[5u*MR*CC];
__device__ __align__(1024) __half g_act_lo[5u*MR*CC];
__device__ __align__(1024) __half g_g_hi[MR*AA];
__device__ __align__(1024) __half g_g_lo[MR*AA];
__device__ __align__(1024) __half g_mixt_hi[MR*NMIX];   // A-layout, kc=8
__device__ __align__(1024) __half g_mixt_lo[MR*NMIX];
__device__ __align__(1024) __half g_td_hi[MR*NTD];      // A-layout, kc=4
__device__ __align__(1024) __half g_td_lo[MR*NTD];
// B-side operands: single fp16, tiled B-layout
__device__ __align__(1024) __half g_w1_h[CC*NMIX];      // kc=64
__device__ __align__(1024) __half g_tdw1_h[CC*NTD];     // kc=64
__device__ __align__(1024) __half g_W_h[5u*CC*AA];      // kc=64
__device__ __align__(1024) __half g_w2_h[5u*TMX*CC];    // kc=1 per f
__device__ __align__(1024) __half g_tdw2_h[NTD*AA];     // kc=4 (K padded 64->128)
// fp32 intermediates
__device__ float g_r[MR*AA];
__device__ float g_k[MR*AA];
__device__ float g_v[MR*AA];
__device__ float g_gate[MR*AA];
__device__ float g_w[MR*AA];
__device__ float g_xo[MR*AA];

// ---------------- helpers ----------------
__device__ __forceinline__ uint32_t smem_u32(const void* p) {
    return (uint32_t)__cvta_generic_to_shared(p);
}
template<int EPI>
__device__ __forceinline__ float hepi(float a) {
    if (EPI == 2) return a / (1.0f + expf(-a));
    return a;
}
__device__ __forceinline__ void mbar_wait(uint32_t mb, uint32_t parity) {
    asm volatile(
        "{\n\t.reg .pred P;\n\t"
        "WL%=:\n\t"
        "mbarrier.try_wait.parity.shared.b64 P, [%0], %1;\n\t"
        "@P bra WD%=;\n\t"
        "bra WL%=;\n\t"
        "WD%=:\n\t}"
        :: "r"(mb), "r"(parity) : "memory");
}
__device__ __forceinline__ long a_tile_byte_k(int m, int k0, int nc) {
    int r = m & 127, g = (k0 & 31) >> 3;
    return ((long)((m >> 7) * nc + (k0 >> 5))) * 8192 + r*64 + ((g ^ ((r>>1)&3)) << 4);
}
__device__ __forceinline__ long b_tile_byte_k(int k, int n0, int nc) {
    int kr = k & 31, gn = (n0 & 127) >> 3;
    return ((long)((n0 >> 7) * nc + (k >> 5))) * 8192 + kr*256 + ((gn ^ (kr&7)) << 4);
}
__device__ __forceinline__ long a_tile_byte(int m, int k0) { return a_tile_byte_k(m, k0, KCHUNKS); }
__device__ __forceinline__ long b_tile_byte(int k, int n0) { return b_tile_byte_k(k, n0, KCHUNKS); }

__device__ __forceinline__ void split8_store_h(const float* v, char* hi, char* lo, long byte) {
    uint32_t ph[4], pl[4];
    #pragma unroll
    for (int j = 0; j < 4; j++) {
        __half h0 = __float2half_rn(v[2*j]);
        __half h1 = __float2half_rn(v[2*j+1]);
        float l0 = v[2*j]   - __half2float(h0);
        float l1 = v[2*j+1] - __half2float(h1);
        __half2 hh; hh.x = h0; hh.y = h1;
        __half2 ll; ll.x = __float2half_rn(l0); ll.y = __float2half_rn(l1);
        ph[j] = *(uint32_t*)&hh; pl[j] = *(uint32_t*)&ll;
    }
    *(uint4*)(hi + byte) = make_uint4(ph[0], ph[1], ph[2], ph[3]);
    *(uint4*)(lo + byte) = make_uint4(pl[0], pl[1], pl[2], pl[3]);
}
__device__ __forceinline__ void pack8_store_h(const float* v, char* dst, long byte) {
    uint32_t p[4];
    #pragma unroll
    for (int j = 0; j < 4; j++) {
        __half2 hh; hh.x = __float2half_rn(v[2*j]); hh.y = __float2half_rn(v[2*j+1]);
        p[j] = *(uint32_t*)&hh;
    }
    *(uint4*)(dst + byte) = make_uint4(p[0], p[1], p[2], p[3]);
}
__device__ __forceinline__ void split2_store_h(float v0, float v1, char* hi, char* lo, long byte) {
    __half h0 = __float2half_rn(v0), h1 = __float2half_rn(v1);
    __half2 hh; hh.x = h0; hh.y = h1;
    __half2 ll; ll.x = __float2half_rn(v0 - __half2float(h0));
    ll.y = __float2half_rn(v1 - __half2float(h1));
    *(__half2*)(hi + byte) = hh;
    *(__half2*)(lo + byte) = ll;
}

// ---------------- fused prep + xxx -> tiled A-layout (also resets tile counters) ----------------
__global__ void mixx_kernel(const float* __restrict__ x,
                            const float* __restrict__ maa_x,
                            const int* __restrict__ positions,
                            const float* __restrict__ shift_state) {
    int idx = blockIdx.x * blockDim.x + threadIdx.x;
    if (idx < 8) g_ctr[idx] = 0;
    if (idx >= MR*CC/8) return;
    int m  = idx >> 8;
    int k0 = (idx & 255) << 3;
    int b  = m / TT;
    float rst = (positions[b*TT] == 0) ? -100.0f : 0.0f;
    float erst = expf(rst);
    float v[8];
    #pragma unroll
    for (int e = 0; e < 8; e++) {
        int c = k0 + e;
        float sh = shift_state[b*CC + c] * erst;
        if ((m % TT) == 0) g_shift[b*CC + c] = sh;
        float xv = x[(long)m*CC + c];
        v[e] = xv + (sh - xv) * maa_x[c];
    }
    if ((m % TT) == 0 && k0 == 0) g_reset[b] = rst;
    split8_store_h(v, (char*)g_xxx_hi, (char*)g_xxx_lo, a_tile_byte(m, k0));
}

// ---------------- pad fp32 [K=2048,Nsrc] -> fp16 tiled B-layout (kc=64) ----------------
__global__ void padsplit_kernel(const float* __restrict__ src,
                                __half* __restrict__ dst,
                                int Nsrc, int Ndst) {
    int idx = blockIdx.x * blockDim.x + threadIdx.x;
    int gpr = Ndst >> 3;
    if (idx >= KDIM*gpr) return;
    int k  = idx / gpr;
    int n0 = (idx % gpr) << 3;
    float v[8];
    #pragma unroll
    for (int e = 0; e < 8; e++) {
        int n = n0 + e;
        v[e] = (n < Nsrc) ? src[(long)k*Nsrc + n] : 0.0f;
    }
    pack8_store_h(v, (char*)dst, b_tile_byte(k, n0));
}

// ---------------- fused pack of all five [2048,2048] weights -> B-layout ----------------
struct W5 { const float* p[5]; };
__global__ void pack5_kernel(W5 w, __half* __restrict__ dst) {
    int idx = blockIdx.x * blockDim.x + threadIdx.x;
    const int per_f = KDIM * (AA/8);
    if (idx >= 5*per_f) return;
    int f = idx / per_f, rem = idx % per_f;
    int k = rem / (AA/8);
    int n0 = (rem % (AA/8)) << 3;
    const float* src = w.p[f];
    float v[8];
    #pragma unroll
    for (int e = 0; e < 8; e++) v[e] = src[(long)k*AA + n0 + e];
    pack8_store_h(v, (char*)dst + (long)f*CC*AA*2, b_tile_byte(k, n0));
}

// ---------------- pack w2 [5,32,CC] -> 5 x B-layout (kc=1) ----------------
__global__ void pack_w2_kernel(const float* __restrict__ w2, __half* __restrict__ dst) {
    int idx = blockIdx.x * blockDim.x + threadIdx.x;
    const int per_f = TMX * (CC/8);
    if (idx >= 5*per_f) return;
    int f = idx / per_f, rem = idx % per_f;
    int k = rem / (CC/8);
    int n0 = (rem % (CC/8)) << 3;
    float v[8];
    #pragma unroll
    for (int e = 0; e < 8; e++) v[e] = w2[(long)f*TMX*CC + (long)k*CC + n0 + e];
    pack8_store_h(v, (char*)dst + (long)f*TMX*CC*2, b_tile_byte_k(k, n0, 1));
}

// ---------------- pack tdw2 [64,AA] -> B-layout K padded to 128 (kc=4) ----------------
__global__ void pack_tdw2_kernel(const float* __restrict__ tdw2, __half* __restrict__ dst) {
    int idx = blockIdx.x * blockDim.x + threadIdx.x;
    if (idx >= NTD*(AA/8)) return;
    int k = idx / (AA/8);
    int n0 = (idx % (AA/8)) << 3;
    float v[8];
    #pragma unroll
    for (int e = 0; e < 8; e++) v[e] = (k < TDX) ? tdw2[(long)k*AA + n0 + e] : 0.0f;
    pack8_store_h(v, (char*)dst, b_tile_byte_k(k, n0, 4));
}

// ---------------- core GEMM accumulate: MI*32 x 128 tile, NC chunks of K=32 ----------------
template<int MI, int NC>
__device__ __forceinline__ void gemm_core(
        uint32_t sb, uint64_t* mb_full,
        const char* pA0, const char* pA1, const char* pB,
        int tid, int lr, int lh, int wm, int wn,
        float acc[MI][4][4]) {
    constexpr int ASLOT = MI * 2048;
    constexpr int STGB  = 2*ASLOT + 8192;

    if (tid == 0) {
        #pragma unroll
        for (int s = 0; s < NST; s++)
            asm volatile("mbarrier.init.shared.b64 [%0], 1;"
                         :: "r"(smem_u32(&mb_full[s])) : "memory");
    }
    __syncthreads();

    auto arm = [&](int c) {
        int s = c % NST;
        uint32_t st = sb + s*STGB;
        uint32_t mb = smem_u32(&mb_full[s]);
        long o = (long)c * 8192;
        asm volatile("mbarrier.arrive.expect_tx.shared.b64 _, [%0], %1;"
                     :: "r"(mb), "r"((uint32_t)STGB) : "memory");
        asm volatile("cp.async.bulk.shared::cluster.global.mbarrier::complete_tx::bytes [%0], [%1], %2, [%3];"
                     :: "r"(st),           "l"(pA0 + o), "r"((uint32_t)ASLOT), "r"(mb) : "memory");
        asm volatile("cp.async.bulk.shared::cluster.global.mbarrier::complete_tx::bytes [%0], [%1], %2, [%3];"
                     :: "r"(st + ASLOT),   "l"(pA1 + o), "r"((uint32_t)ASLOT), "r"(mb) : "memory");
        asm volatile("cp.async.bulk.shared::cluster.global.mbarrier::complete_tx::bytes [%0], [%1], %2, [%3];"
                     :: "r"(st + 2*ASLOT), "l"(pB + o),  "r"(8192u), "r"(mb) : "memory");
    };
    constexpr int PRIME = (NC < NST) ? NC : NST;
    if (tid == 0) {
        #pragma unroll
        for (int c = 0; c < PRIME; c++) arm(c);
    }

    #pragma unroll
    for (int a=0;a<MI;a++)
        #pragma unroll
        for (int b2=0;b2<4;b2++)
            #pragma unroll
            for (int d=0;d<4;d++) acc[a][b2][d]=0.f;

    #pragma unroll 1
    for (int c = 0; c < NC; c++) {
        int s = c % NST;
        uint32_t par = (uint32_t)((c / NST) & 1);
        mbar_wait(smem_u32(&mb_full[s]), par);

        uint32_t st = sb + s*STGB;
        #pragma unroll
        for (int ks = 0; ks < 2; ks++) {
            uint32_t ah[MI][4], al[MI][4], bh[4][2];
            #pragma unroll
            for (int mi = 0; mi < MI; mi++) {
                int row = wm*(MI*16) + mi*16 + lr;
                int g = ks*2 + lh;
                uint32_t off = row*64 + ((g ^ ((row>>1)&3)) << 4);
                asm volatile("ldmatrix.sync.aligned.m8n8.x4.shared.b16 {%0,%1,%2,%3}, [%4];"
                    : "=r"(ah[mi][0]),"=r"(ah[mi][1]),"=r"(ah[mi][2]),"=r"(ah[mi][3])
                    : "r"(st + off));
                asm volatile("ldmatrix.sync.aligned.m8n8.x4.shared.b16 {%0,%1,%2,%3}, [%4];"
                    : "=r"(al[mi][0]),"=r"(al[mi][1]),"=r"(al[mi][2]),"=r"(al[mi][3])
                    : "r"(st + ASLOT + off));
            }
            #pragma unroll
            for (int ni = 0; ni < 4; ni++) {
                int kr = ks*16 + lr;
                int gn = wn*4 + ni;
                uint32_t off = kr*256 + ((gn ^ (kr & 7)) << 4);
                asm volatile("ldmatrix.sync.aligned.m8n8.x2.trans.shared.b16 {%0,%1}, [%2];"
                    : "=r"(bh[ni][0]),"=r"(bh[ni][1]) : "r"(st + 2*ASLOT + off));
            }
            #pragma unroll
            for (int mi = 0; mi < MI; mi++)
                #pragma unroll
                for (int ni = 0; ni < 4; ni++)
                    asm volatile("mma.sync.aligned.m16n8k16.row.col.f32.f16.f16.f32 "
                        "{%0,%1,%2,%3}, {%4,%5,%6,%7}, {%8,%9}, {%0,%1,%2,%3};"
                        : "+f"(acc[mi][ni][0]),"+f"(acc[mi][ni][1]),
                          "+f"(acc[mi][ni][2]),"+f"(acc[mi][ni][3])
                        : "r"(ah[mi][0]),"r"(ah[mi][1]),"r"(ah[mi][2]),"r"(ah[mi][3]),
                          "r"(bh[ni][0]),"r"(bh[ni][1]));
            #pragma unroll
            for (int mi = 0; mi < MI; mi++)
                #pragma unroll
                for (int ni = 0; ni < 4; ni++)
                    asm volatile("mma.sync.aligned.m16n8k16.row.col.f32.f16.f16.f32 "
                        "{%0,%1,%2,%3}, {%4,%5,%6,%7}, {%8,%9}, {%0,%1,%2,%3};"
                        : "+f"(acc[mi][ni][0]),"+f"(acc[mi][ni][1]),
                          "+f"(acc[mi][ni][2]),"+f"(acc[mi][ni][3])
                        : "r"(al[mi][0]),"r"(al[mi][1]),"r"(al[mi][2]),"r"(al[mi][3]),
                          "r"(bh[ni][0]),"r"(bh[ni][1]));
        }
        __syncthreads();
        if (tid == 0 && c + NST < NC) arm(c + NST);
    }
}

// ---------------- persistent big GEMM (fp32 out, EPI 0/2) ----------------
template<int EPI>
__global__ void __launch_bounds__(256, 2)
hgemm2p(const __half* __restrict__ Ahi, const __half* __restrict__ Alo,
        const __half* __restrict__ B, float* __restrict__ C, int N, int ctrIdx) {
    extern __shared__ __align__(1024) unsigned char sm[];
    __shared__ __align__(8) uint64_t mb_full[NST];
    __shared__ int s_tile;
    const int tid = threadIdx.x;
    const int lane = tid & 31, warp = tid >> 5;
    const int wm = warp >> 2, wn = warp & 3;
    const int lr = lane & 15, lh = lane >> 4;
    const int numTiles = (MR/128) * (N/128);
    const int rowTiles = MR/128;

    if (tid == 0) s_tile = atomicAdd(&g_ctr[ctrIdx], 1);
    __syncthreads();
    int tile = s_tile;

    while (tile < numTiles) {
        int by = tile % rowTiles;
        int bx = tile / rowTiles;
        int rowBase = by * 128, colBase = bx * 128;
        const char* pA0 = (const char*)Ahi + (long)(rowBase >> 7) * KCHUNKS * 8192;
        const char* pA1 = (const char*)Alo + (long)(rowBase >> 7) * KCHUNKS * 8192;
        const char* pB  = (const char*)B   + (long)(colBase >> 7) * KCHUNKS * 8192;
        float acc[4][4][4];
        gemm_core<4, KCHUNKS>(smem_u32(sm), mb_full, pA0, pA1, pB, tid, lr, lh, wm, wn, acc);
        #pragma unroll
        for (int mi = 0; mi < 4; mi++) {
            int r0 = rowBase + wm*64 + mi*16 + (lane >> 2);
            #pragma unroll
            for (int ni = 0; ni < 4; ni++) {
                int c0 = colBase + wn*32 + ni*8 + (lane & 3)*2;
                float2 v0, v1;
                v0.x = hepi<EPI>(acc[mi][ni][0]); v0.y = hepi<EPI>(acc[mi][ni][1]);
                v1.x = hepi<EPI>(acc[mi][ni][2]); v1.y = hepi<EPI>(acc[mi][ni][3]);
                *(float2*)&C[(long)r0*N + c0]     = v0;
                *(float2*)&C[(long)(r0+8)*N + c0] = v1;
            }
        }
        __syncthreads();
        if (tid == 0) s_tile = atomicAdd(&g_ctr[ctrIdx], 1);
        __syncthreads();
        tile = s_tile;
    }
}

// ---------------- tanh GEMM -> split-fp16 A-layout out (mixt: NCOUT=8, td: NCOUT=4) ----------------
template<int MI, int NCOUT>
__global__ void __launch_bounds__(256, 2)
hgemm_tanh_split(const __half* __restrict__ Ahi, const __half* __restrict__ Alo,
                 const __half* __restrict__ B,
                 __half* __restrict__ Ohi, __half* __restrict__ Olo) {
    extern __shared__ __align__(1024) unsigned char sm[];
    __shared__ __align__(8) uint64_t mb_full[NST];
    const int tid = threadIdx.x;
    const int lane = tid & 31, warp = tid >> 5;
    const int wm = warp >> 2, wn = warp & 3;
    const int lr = lane & 15, lh = lane >> 4;
    const int rowBase = blockIdx.y * (MI*32), colBase = blockIdx.x * 128;
    const long aoff = (long)(rowBase >> 7) * KCHUNKS * 8192 + (long)((rowBase >> 5) & 3) * 2048;
    const char* pA0 = (const char*)Ahi + aoff;
    const char* pA1 = (const char*)Alo + aoff;
    const char* pB  = (const char*)B + (long)(colBase >> 7) * KCHUNKS * 8192;
    float acc[MI][4][4];
    gemm_core<MI, KCHUNKS>(smem_u32(sm), mb_full, pA0, pA1, pB, tid, lr, lh, wm, wn, acc);
    #pragma unroll
    for (int mi = 0; mi < MI; mi++) {
        int r0 = rowBase + wm*(MI*16) + mi*16 + (lane >> 2);
        #pragma unroll
        for (int ni = 0; ni < 4; ni++) {
            int c0 = colBase + wn*32 + ni*8 + (lane & 3)*2;
            int e2 = (c0 & 7) * 2;
            long ba = a_tile_byte_k(r0,   c0 & ~7, NCOUT) + e2;
            long bb = a_tile_byte_k(r0+8, c0 & ~7, NCOUT) + e2;
            split2_store_h(tanhf(acc[mi][ni][0]), tanhf(acc[mi][ni][1]), (char*)Ohi, (char*)Olo, ba);
            split2_store_h(tanhf(acc[mi][ni][2]), tanhf(acc[mi][ni][3]), (char*)Ohi, (char*)Olo, bb);
        }
    }
}

// ---------------- mix GEMM (K=32, per-f) -> act_f split-fp16 A-layout ----------------
struct MixP { const float* maa[5]; };
__global__ void __launch_bounds__(256, 2)
hgemm_mix(const __half* __restrict__ Mhi, const __half* __restrict__ Mlo,
          const __half* __restrict__ W2, MixP mp,
          const float* __restrict__ x,
          __half* __restrict__ Ohi, __half* __restrict__ Olo) {
    extern __shared__ __align__(1024) unsigned char sm[];
    __shared__ __align__(8) uint64_t mb_full[NST];
    const int tid = threadIdx.x;
    const int lane = tid & 31, warp = tid >> 5;
    const int wm = warp >> 2, wn = warp & 3;
    const int lr = lane & 15, lh = lane >> 4;
    const int f = blockIdx.z;
    const int rowBase = blockIdx.y * 128, colBase = blockIdx.x * 128;
    const char* pA0 = (const char*)Mhi + ((long)(rowBase >> 7) * 8 + f) * 8192;
    const char* pA1 = (const char*)Mlo + ((long)(rowBase >> 7) * 8 + f) * 8192;
    const char* pB  = (const char*)W2 + (long)f*TMX*CC*2 + (long)(colBase >> 7) * 8192;
    float acc[4][4][4];
    gemm_core<4, 1>(smem_u32(sm), mb_full, pA0, pA1, pB, tid, lr, lh, wm, wn, acc);

    const float* maa = mp.maa[f];
    char* oh = (char*)Ohi + (long)f*MR*CC*2;
    char* ol = (char*)Olo + (long)f*MR*CC*2;
    #pragma unroll
    for (int mi = 0; mi < 4; mi++) {
        int r0 = rowBase + wm*64 + mi*16 + (lane >> 2);
        int b0 = r0 / TT, b1 = (r0+8) / TT;
        #pragma unroll
        for (int ni = 0; ni < 4; ni++) {
            int c0 = colBase + wn*32 + ni*8 + (lane & 3)*2;
            float ma0 = maa[c0], ma1 = maa[c0+1];
            int e2 = (c0 & 7) * 2;
            {
                float xv0 = x[(long)r0*CC + c0], xv1 = x[(long)r0*CC + c0 + 1];
                float s0 = g_shift[b0*CC + c0], s1 = g_shift[b0*CC + c0 + 1];
                float v0 = xv0 + (s0 - xv0) * (ma0 + acc[mi][ni][0]);
                float v1 = xv1 + (s1 - xv1) * (ma1 + acc[mi][ni][1]);
                split2_store_h(v0, v1, oh, ol, a_tile_byte_k(r0, c0 & ~7, KCHUNKS) + e2);
            }
            {
                float xv0 = x[(long)(r0+8)*CC + c0], xv1 = x[(long)(r0+8)*CC + c0 + 1];
                float s0 = g_shift[b1*CC + c0], s1 = g_shift[b1*CC + c0 + 1];
                float v0 = xv0 + (s0 - xv0) * (ma0 + acc[mi][ni][2]);
                float v1 = xv1 + (s1 - xv1) * (ma1 + acc[mi][ni][3]);
                split2_store_h(v0, v1, oh, ol, a_tile_byte_k(r0+8, c0 & ~7, KCHUNKS) + e2);
            }
        }
    }
}

// ---------------- decay GEMM (K=128, NC=4): w = -exp(tdecay + td @ tdw2) ----------------
__global__ void __launch_bounds__(256, 2)
hgemm_decay(const __half* __restrict__ Ahi, const __half* __restrict__ Alo,
            const __half* __restrict__ B, const float* __restrict__ p1,
            float* __restrict__ C) {
    extern __shared__ __align__(1024) unsigned char sm[];
    __shared__ __align__(8) uint64_t mb_full[NST];
    const int tid = threadIdx.x;
    const int lane = tid & 31, warp = tid >> 5;
    const int wm = warp >> 2, wn = warp & 3;
    const int lr = lane & 15, lh = lane >> 4;
    const int rowBase = blockIdx.y * 128, colBase = blockIdx.x * 128;
    const char* pA0 = (const char*)Ahi + (long)(rowBase >> 7) * 4 * 8192;
    const char* pA1 = (const char*)Alo + (long)(rowBase >> 7) * 4 * 8192;
    const char* pB  = (const char*)B + (long)(colBase >> 7) * 4 * 8192;
    float acc[4][4][4];
    gemm_core<4, 4>(smem_u32(sm), mb_full, pA0, pA1, pB, tid, lr, lh, wm, wn, acc);
    #pragma unroll
    for (int mi = 0; mi < 4; mi++) {
        int r0 = rowBase + wm*64 + mi*16 + (lane >> 2);
        #pragma unroll
        for (int ni = 0; ni < 4; ni++) {
            int c0 = colBase + wn*32 + ni*8 + (lane & 3)*2;
            float p0 = p1[c0], pp1 = p1[c0+1];
            float2 v0, v1;
            v0.x = -expf(p0  + acc[mi][ni][0]); v0.y = -expf(pp1 + acc[mi][ni][1]);
            v1.x = -expf(p0  + acc[mi][ni][2]); v1.y = -expf(pp1 + acc[mi][ni][3]);
            *(float2*)&C[(long)r0*AA + c0]     = v0;
            *(float2*)&C[(long)(r0+8)*AA + c0] = v1;
        }
    }
}

// ---------------- recurrence: split-K, 128 threads per (b,h), 4-way o ILP ----------------
__global__ void scan_kernel(const float* __restrict__ kv_state,
                            const float* __restrict__ faaaa) {
    int b = blockIdx.x / HH, h = blockIdx.x % HH;
    int tid = threadIdx.x;
    int half = tid >> 6;
    int v = tid & 63;
    __shared__ float r_sh[2][ZZ], k_sh[2][ZZ], ew_sh[2][ZZ], o_sh[2][ZZ];
    __shared__ float part[2][2];

    float S[32];
    const float* Sin = kv_state + ((long)(b*HH + h) * ZZ) * ZZ;
    #pragma unroll
    for (int j=0;j<32;j++) S[j] = Sin[(half*32+j)*ZZ + v];

    float uv = faaaa[h*ZZ + v];
    long base = (long)(b*TT) * AA + h*ZZ;
    float reset_b = g_reset[b];
    int lane = tid & 31, wrp = tid >> 5;

    float rv = 0.f, kvv = 0.f, wl = 0.f;
    float vv = g_v[base + v];
    if (half == 0) {
        rv  = g_r[base + v];
        kvv = g_k[base + v];
        wl  = g_w[base + v] + reset_b;
    }

    for (int t=0;t<TT;t++) {
        int bi = t & 1;
        if (half == 0) {
            r_sh[bi][v]  = rv;
            k_sh[bi][v]  = kvv;
            ew_sh[bi][v] = expf(wl);
            float p = rv * uv * kvv;
            #pragma unroll
            for (int off=16; off; off >>= 1) p += __shfl_xor_sync(0xffffffffu, p, off);
            if (lane == 0) part[bi][wrp] = p;
        }
        __syncthreads();

        float rv_n = 0.f, kv_n = 0.f, wl_n = 0.f, vv_n = 0.f;
        if (t + 1 < TT) {
            long nb = base + (long)(t+1)*AA;
            vv_n = g_v[nb + v];
            if (half == 0) {
                rv_n = g_r[nb + v];
                kv_n = g_k[nb + v];
                wl_n = g_w[nb + v];
            }
        }

        float ruk = part[bi][0] + part[bi][1];
        const float* rs  = r_sh[bi]  + half*32;
        const float* ks  = k_sh[bi]  + half*32;
        const float* ews = ew_sh[bi] + half*32;
        float o0 = 0.f, o1 = 0.f, o2 = 0.f, o3 = 0.f;
        #pragma unroll
        for (int j=0;j<32;j+=4) {
            o0 = fmaf(rs[j],   S[j],   o0); S[j]   = fmaf(ews[j],   S[j],   ks[j]*vv);
            o1 = fmaf(rs[j+1], S[j+1], o1); S[j+1] = fmaf(ews[j+1], S[j+1], ks[j+1]*vv);
            o2 = fmaf(rs[j+2], S[j+2], o2); S[j+2] = fmaf(ews[j+2], S[j+2], ks[j+2]*vv);
            o3 = fmaf(rs[j+3], S[j+3], o3); S[j+3] = fmaf(ews[j+3], S[j+3], ks[j+3]*vv);
        }
        float o = (o0 + o1) + (o2 + o3);
        if (half == 1) o_sh[bi][v] = o;
        __syncthreads();
        if (half == 0)
            g_xo[base + (long)t*AA + v] = o + o_sh[bi][v] + ruk * vv;

        rv = rv_n; kvv = kv_n; wl = wl_n; vv = vv_n;
    }
}

// ---------------- groupnorm + gate -> tiled A-layout (fp16 split) ----------------
__global__ void gn_gate_kernel(const float* __restrict__ ln_w,
                               const float* __restrict__ ln_b) {
    int gid = blockIdx.x * (blockDim.x >> 5) + (threadIdx.x >> 5);
    int lane = threadIdx.x & 31;
    if (gid >= MR*HH) return;
    int bt = gid / HH, h = gid % HH;
    long base = (long)bt*CC + h*ZZ;
    float x0 = g_xo[base + lane];
    float x1 = g_xo[base + lane + 32];
    float s = x0 + x1;
    #pragma unroll
    for (int off=16; off; off >>= 1) s += __shfl_xor_sync(0xffffffffu, s, off);
    float mu = s * (1.0f/64.0f);
    float d0 = x0 - mu, d1 = x1 - mu;
    float q = d0*d0 + d1*d1;
    #pragma unroll
    for (int off=16; off; off >>= 1) q += __shfl_xor_sync(0xffffffffu, q, off);
    float rs = rsqrtf(q * (1.0f/64.0f) + EPS_GN);
    int c0 = h*ZZ + lane, c1 = c0 + 32;
    float g0 = (d0 * rs * ln_w[c0] + ln_b[c0]) * g_gate[base + lane];
    float g1 = (d1 * rs * ln_w[c1] + ln_b[c1]) * g_gate[base + lane + 32];
    long b0 = a_tile_byte(bt, c0 & ~7) + (c0 & 7)*2;
    long b1 = a_tile_byte(bt, c1 & ~7) + (c1 & 7)*2;
    __half h0 = __float2half_rn(g0);
    __half h1 = __float2half_rn(g1);
    *(__half*)((char*)g_g_hi + b0) = h0;
    *(__half*)((char*)g_g_lo + b0) = __float2half_rn(g0 - __half2float(h0));
    *(__half*)((char*)g_g_hi + b1) = h1;
    *(__half*)((char*)g_g_lo + b1) = __float2half_rn(g1 - __half2float(h1));
}

// ---------------- launch ----------------
extern "C" void kernel_launch(void* const* d_in, const int* in_sizes, int n_in,
                              void* d_out, int out_size) {
    const float* x        = (const float*)d_in[0];
    const int*   pos      = (const int*)  d_in[1];
    const float* kv_state = (const float*)d_in[2];
    const float* shift_st = (const float*)d_in[3];
    const float* maa_x    = (const float*)d_in[4];
    const float* maa_f[5] = { (const float*)d_in[5], (const float*)d_in[6],
                              (const float*)d_in[7], (const float*)d_in[8],
                              (const float*)d_in[9] };       // w,k,v,r,g
    const float* w1       = (const float*)d_in[10];
    const float* w2       = (const float*)d_in[11];
    const float* tdecay   = (const float*)d_in[12];
    const float* tdw1     = (const float*)d_in[13];
    const float* tdw2     = (const float*)d_in[14];
    const float* faaaa    = (const float*)d_in[15];
    const float* Wmat[5]  = { (const float*)d_in[16], (const float*)d_in[17],
                              (const float*)d_in[18], (const float*)d_in[19],
                              (const float*)d_in[20] };      // W_r,W_k,W_v,W_g,W_o
    const float* ln_w     = (const float*)d_in[21];
    const float* ln_b     = (const float*)d_in[22];
    float* out = (float*)d_out;

    float *rb, *kb, *vb, *gateb, *wb;
    __half *xxh, *xxl, *w1h, *tdh, *Wh, *ah, *al, *gh, *gl;
    __half *mth, *mtl, *tdsh, *tdsl, *w2h, *tdw2h;
    cudaGetSymbolAddress((void**)&rb,   g_r);
    cudaGetSymbolAddress((void**)&kb,   g_k);
    cudaGetSymbolAddress((void**)&vb,   g_v);
    cudaGetSymbolAddress((void**)&gateb,g_gate);
    cudaGetSymbolAddress((void**)&wb,   g_w);
    cudaGetSymbolAddress((void**)&xxh,  g_xxx_hi);
    cudaGetSymbolAddress((void**)&xxl,  g_xxx_lo);
    cudaGetSymbolAddress((void**)&w1h,  g_w1_h);
    cudaGetSymbolAddress((void**)&tdh,  g_tdw1_h);
    cudaGetSymbolAddress((void**)&Wh,   g_W_h);
    cudaGetSymbolAddress((void**)&ah,   g_act_hi);
    cudaGetSymbolAddress((void**)&al,   g_act_lo);
    cudaGetSymbolAddress((void**)&gh,   g_g_hi);
    cudaGetSymbolAddress((void**)&gl,   g_g_lo);
    cudaGetSymbolAddress((void**)&mth,  g_mixt_hi);
    cudaGetSymbolAddress((void**)&mtl,  g_mixt_lo);
    cudaGetSymbolAddress((void**)&tdsh, g_td_hi);
    cudaGetSymbolAddress((void**)&tdsl, g_td_lo);
    cudaGetSymbolAddress((void**)&w2h,  g_w2_h);
    cudaGetSymbolAddress((void**)&tdw2h,g_tdw2_h);

    const int SM128 = 3 * (2*8192 + 8192);      // MI=4: 73728
    const int SM64  = 3 * (2*4096 + 8192);      // MI=2: 49152
    const int SMMIX = (2*8192 + 8192);          // MI=4, NC=1: 24576
    cudaFuncSetAttribute((const void*)hgemm2p<0>,           cudaFuncAttributeMaxDynamicSharedMemorySize, SM128);
    cudaFuncSetAttribute((const void*)hgemm2p<2>,           cudaFuncAttributeMaxDynamicSharedMemorySize, SM128);
    cudaFuncSetAttribute((const void*)hgemm_tanh_split<2,8>,cudaFuncAttributeMaxDynamicSharedMemorySize, SM64);
    cudaFuncSetAttribute((const void*)hgemm_tanh_split<2,4>,cudaFuncAttributeMaxDynamicSharedMemorySize, SM64);
    cudaFuncSetAttribute((const void*)hgemm_mix,            cudaFuncAttributeMaxDynamicSharedMemorySize, SMMIX);
    cudaFuncSetAttribute((const void*)hgemm_decay,          cudaFuncAttributeMaxDynamicSharedMemorySize, SM128);

    const long WC = (long)CC * AA;
    MixP mp; for (int i=0;i<5;i++) mp.maa[i] = maa_f[i];
    W5 w5; for (int i=0;i<5;i++) w5.p[i] = Wmat[i];

    // ---- fork: weight packs run concurrently with the activation chain ----
    cudaStream_t s2;
    cudaStreamCreate(&s2);
    cudaEvent_t eFork, eJoin;
    cudaEventCreate(&eFork);
    cudaEventCreate(&eJoin);
    cudaEventRecord(eFork, 0);
    cudaStreamWaitEvent(s2, eFork, 0);
    // side stream: all big weight packs
    pack5_kernel<<<(5*KDIM*(AA/8) + 255)/256, 256, 0, s2>>>(w5, Wh);
    padsplit_kernel<<<(KDIM*(NTD/8) + 255)/256, 256, 0, s2>>>(tdw1, tdh, TDX, NTD);
    pack_tdw2_kernel<<<(NTD*(AA/8) + 255)/256, 256, 0, s2>>>(tdw2, tdw2h);
    cudaEventRecord(eJoin, s2);

    // main stream: activation chain
    // 1) fused shift/reset + xxx (zeroes tile counters)
    mixx_kernel<<<(MR*CC/8 + 255)/256, 256>>>(x, maa_x, pos, shift_st);
    // 2) w1 pack (pad 160->256)
    padsplit_kernel<<<(KDIM*(NMIX/8) + 255)/256, 256>>>(w1, w1h, 5*TMX, NMIX);
    // 3) mixt = tanh(xxx @ w1) -> split A-layout (kc=8)   <-- ncu capture slot
    hgemm_tanh_split<2,8><<<dim3(NMIX/128, MR/64), 256, SM64>>>(xxh, xxl, w1h, mth, mtl);
    // 4) w2 pack (kc=1 per f)
    pack_w2_kernel<<<(5*TMX*(CC/8) + 255)/256, 256>>>(w2, w2h);
    // 5) mix GEMMs (all 5 f) -> act split A-layout
    hgemm_mix<<<dim3(CC/128, MR/128, 5), 256, SMMIX>>>(mth, mtl, w2h, mp, x, ah, al);
    // ---- join: packs must be done before projections ----
    cudaStreamWaitEvent(0, eJoin, 0);
    // 6-9) r, k, v, g projections (persistent)
    hgemm2p<0><<<PGRID, 256, SM128>>>(ah + 3L*MR*CC, al + 3L*MR*CC, Wh + 0*WC, rb,    AA, 0);
    hgemm2p<0><<<PGRID, 256, SM128>>>(ah + 1L*MR*CC, al + 1L*MR*CC, Wh + 1*WC, kb,    AA, 1);
    hgemm2p<0><<<PGRID, 256, SM128>>>(ah + 2L*MR*CC, al + 2L*MR*CC, Wh + 2*WC, vb,    AA, 2);
    hgemm2p<2><<<PGRID, 256, SM128>>>(ah + 4L*MR*CC, al + 4L*MR*CC, Wh + 3*WC, gateb, AA, 3);
    // 10) td = tanh(td_in @ tdw1) -> split A-layout (kc=4)
    hgemm_tanh_split<2,4><<<dim3(NTD/128, MR/64), 256, SM64>>>(ah, al, tdh, tdsh, tdsl);
    // 11) w = -exp(time_decay + td @ tdw2)  (tensor, K=128)
    hgemm_decay<<<dim3(AA/128, MR/128), 256, SM128>>>(tdsh, tdsl, tdw2h, tdecay, wb);
    // 12) recurrence
    scan_kernel<<<BB*HH, 128>>>(kv_state, faaaa);
    // 13) groupnorm + gate
    gn_gate_kernel<<<(MR*HH + 7)/8, 256>>>(ln_w, ln_b);
    // 14) out = gated @ W_o (persistent)
    hgemm2p<0><<<PGRID, 256, SM128>>>(gh, gl, Wh + 4*WC, out, CC, 4);
    // (stream/events intentionally not destroyed while capture may be active)
}

// round 15
// speedup vs baseline: 1.0797x; 1.0797x over previous
#include <cuda_runtime.h>
#include <cuda_fp16.h>
#include <math.h>
#include <stdint.h>

// ---------------- problem dims ----------------
#define BB   8
#define TT   512
#define CC   2048
#define HH   32
#define ZZ   64
#define AA   2048
#define MR   (BB*TT)         // 4096
#define TMX  32
#define TDX  64
#define NMIX 256
#define NTD  128
#define EPS_GN (1e-5f * 64.0f)

#define KDIM    2048
#define KCHUNKS 64
#define NST     3
#define PGRID   296

// ---------------- scratch ----------------
__device__ float g_shift[BB*CC];
__device__ float g_reset[BB];
__device__ int   g_ctr[8];
__device__ __align__(1024) __half g_xxx_hi[MR*CC];
__device__ __align__(1024) __half g_xxx_lo[MR*CC];
__device__ __align__(1024) __half g_act_hi[5u*MR*CC];
__device__ __align__(1024) __half g_act_lo[5u*MR*CC];
__device__ __align__(1024) __half g_g_hi[MR*AA];
__device__ __align__(1024) __half g_g_lo[MR*AA];
__device__ __align__(1024) __half g_mixt_hi[MR*NMIX];
__device__ __align__(1024) __half g_mixt_lo[MR*NMIX];
__device__ __align__(1024) __half g_td_hi[MR*NTD];
__device__ __align__(1024) __half g_td_lo[MR*NTD];
__device__ __align__(1024) __half g_w1_h[CC*NMIX];
__device__ __align__(1024) __half g_tdw1_h[CC*NTD];
__device__ __align__(1024) __half g_W_h[5u*CC*AA];
__device__ __align__(1024) __half g_w2_h[5u*TMX*CC];
__device__ __align__(1024) __half g_tdw2_h[NTD*AA];
__device__ float g_r[MR*AA];
__device__ float g_k[MR*AA];
__device__ float g_v[MR*AA];
__device__ float g_gate[MR*AA];
__device__ float g_w[MR*AA];
__device__ float g_xo[MR*AA];

// ---------------- helpers ----------------
__device__ __forceinline__ uint32_t smem_u32(const void* p) {
    return (uint32_t)__cvta_generic_to_shared(p);
}
template<int EPI>
__device__ __forceinline__ float hepi(float a) {
    if (EPI == 2) return a / (1.0f + expf(-a));
    return a;
}
__device__ __forceinline__ void mbar_wait(uint32_t mb, uint32_t parity) {
    asm volatile(
        "{\n\t.reg .pred P;\n\t"
        "WL%=:\n\t"
        "mbarrier.try_wait.parity.shared.b64 P, [%0], %1;\n\t"
        "@P bra WD%=;\n\t"
        "bra WL%=;\n\t"
        "WD%=:\n\t}"
        :: "r"(mb), "r"(parity) : "memory");
}
__device__ __forceinline__ long a_tile_byte_k(int m, int k0, int nc) {
    int r = m & 127, g = (k0 & 31) >> 3;
    return ((long)((m >> 7) * nc + (k0 >> 5))) * 8192 + r*64 + ((g ^ ((r>>1)&3)) << 4);
}
__device__ __forceinline__ long b_tile_byte_k(int k, int n0, int nc) {
    int kr = k & 31, gn = (n0 & 127) >> 3;
    return ((long)((n0 >> 7) * nc + (k >> 5))) * 8192 + kr*256 + ((gn ^ (kr&7)) << 4);
}
__device__ __forceinline__ long a_tile_byte(int m, int k0) { return a_tile_byte_k(m, k0, KCHUNKS); }
__device__ __forceinline__ long b_tile_byte(int k, int n0) { return b_tile_byte_k(k, n0, KCHUNKS); }

__device__ __forceinline__ void split8_store_h(const float* v, char* hi, char* lo, long byte) {
    uint32_t ph[4], pl[4];
    #pragma unroll
    for (int j = 0; j < 4; j++) {
        __half h0 = __float2half_rn(v[2*j]);
        __half h1 = __float2half_rn(v[2*j+1]);
        float l0 = v[2*j]   - __half2float(h0);
        float l1 = v[2*j+1] - __half2float(h1);
        __half2 hh; hh.x = h0; hh.y = h1;
        __half2 ll; ll.x = __float2half_rn(l0); ll.y = __float2half_rn(l1);
        ph[j] = *(uint32_t*)&hh; pl[j] = *(uint32_t*)&ll;
    }
    *(uint4*)(hi + byte) = make_uint4(ph[0], ph[1], ph[2], ph[3]);
    *(uint4*)(lo + byte) = make_uint4(pl[0], pl[1], pl[2], pl[3]);
}
__device__ __forceinline__ void pack8_store_h(const float* v, char* dst, long byte) {
    uint32_t p[4];
    #pragma unroll
    for (int j = 0; j < 4; j++) {
        __half2 hh; hh.x = __float2half_rn(v[2*j]); hh.y = __float2half_rn(v[2*j+1]);
        p[j] = *(uint32_t*)&hh;
    }
    *(uint4*)(dst + byte) = make_uint4(p[0], p[1], p[2], p[3]);
}
__device__ __forceinline__ void split2_store_h(float v0, float v1, char* hi, char* lo, long byte) {
    __half h0 = __float2half_rn(v0), h1 = __float2half_rn(v1);
    __half2 hh; hh.x = h0; hh.y = h1;
    __half2 ll; ll.x = __float2half_rn(v0 - __half2float(h0));
    ll.y = __float2half_rn(v1 - __half2float(h1));
    *(__half2*)(hi + byte) = hh;
    *(__half2*)(lo + byte) = ll;
}

// ---------------- fused prep + xxx (also resets tile counters) ----------------
__global__ void mixx_kernel(const float* __restrict__ x,
                            const float* __restrict__ maa_x,
                            const int* __restrict__ positions,
                            const float* __restrict__ shift_state) {
    int idx = blockIdx.x * blockDim.x + threadIdx.x;
    if (idx < 8) g_ctr[idx] = 0;
    if (idx >= MR*CC/8) return;
    int m  = idx >> 8;
    int k0 = (idx & 255) << 3;
    int b  = m / TT;
    float rst = (positions[b*TT] == 0) ? -100.0f : 0.0f;
    float erst = expf(rst);
    float v[8];
    #pragma unroll
    for (int e = 0; e < 8; e++) {
        int c = k0 + e;
        float sh = shift_state[b*CC + c] * erst;
        if ((m % TT) == 0) g_shift[b*CC + c] = sh;
        float xv = x[(long)m*CC + c];
        v[e] = xv + (sh - xv) * maa_x[c];
    }
    if ((m % TT) == 0 && k0 == 0) g_reset[b] = rst;
    split8_store_h(v, (char*)g_xxx_hi, (char*)g_xxx_lo, a_tile_byte(m, k0));
}

// ---------------- pad fp32 [K=2048,Nsrc] -> fp16 tiled B-layout ----------------
__global__ void padsplit_kernel(const float* __restrict__ src,
                                __half* __restrict__ dst,
                                int Nsrc, int Ndst) {
    int idx = blockIdx.x * blockDim.x + threadIdx.x;
    int gpr = Ndst >> 3;
    if (idx >= KDIM*gpr) return;
    int k  = idx / gpr;
    int n0 = (idx % gpr) << 3;
    float v[8];
    #pragma unroll
    for (int e = 0; e < 8; e++) {
        int n = n0 + e;
        v[e] = (n < Nsrc) ? src[(long)k*Nsrc + n] : 0.0f;
    }
    pack8_store_h(v, (char*)dst, b_tile_byte(k, n0));
}

// ---------------- fused pack of all five [2048,2048] weights ----------------
struct W5 { const float* p[5]; };
__global__ void pack5_kernel(W5 w, __half* __restrict__ dst) {
    int idx = blockIdx.x * blockDim.x + threadIdx.x;
    const int per_f = KDIM * (AA/8);
    if (idx >= 5*per_f) return;
    int f = idx / per_f, rem = idx % per_f;
    int k = rem / (AA/8);
    int n0 = (rem % (AA/8)) << 3;
    const float* src = w.p[f];
    float v[8];
    #pragma unroll
    for (int e = 0; e < 8; e++) v[e] = src[(long)k*AA + n0 + e];
    pack8_store_h(v, (char*)dst + (long)f*CC*AA*2, b_tile_byte(k, n0));
}

// ---------------- pack w2 [5,32,CC] -> 5 x B-layout (kc=1) ----------------
__global__ void pack_w2_kernel(const float* __restrict__ w2, __half* __restrict__ dst) {
    int idx = blockIdx.x * blockDim.x + threadIdx.x;
    const int per_f = TMX * (CC/8);
    if (idx >= 5*per_f) return;
    int f = idx / per_f, rem = idx % per_f;
    int k = rem / (CC/8);
    int n0 = (rem % (CC/8)) << 3;
    float v[8];
    #pragma unroll
    for (int e = 0; e < 8; e++) v[e] = w2[(long)f*TMX*CC + (long)k*CC + n0 + e];
    pack8_store_h(v, (char*)dst + (long)f*TMX*CC*2, b_tile_byte_k(k, n0, 1));
}

// ---------------- pack tdw2 [64,AA] -> B-layout K padded to 128 (kc=4) ----------------
__global__ void pack_tdw2_kernel(const float* __restrict__ tdw2, __half* __restrict__ dst) {
    int idx = blockIdx.x * blockDim.x + threadIdx.x;
    if (idx >= NTD*(AA/8)) return;
    int k = idx / (AA/8);
    int n0 = (idx % (AA/8)) << 3;
    float v[8];
    #pragma unroll
    for (int e = 0; e < 8; e++) v[e] = (k < TDX) ? tdw2[(long)k*AA + n0 + e] : 0.0f;
    pack8_store_h(v, (char*)dst, b_tile_byte_k(k, n0, 4));
}

// ---------------- core GEMM: MI*32 x 128 tile, NC K-chunks, SPLIT=1 -> hi+lo A ----------------
template<int MI, int NC, int SPLIT>
__device__ __forceinline__ void gemm_core(
        uint32_t sb, uint64_t* mb_full,
        const char* pA0, const char* pA1, const char* pB,
        int tid, int lr, int lh, int wm, int wn,
        float acc[MI][4][4]) {
    constexpr int ASLOT = MI * 2048;
    constexpr int NAB   = SPLIT ? 2 : 1;
    constexpr int STGB  = NAB*ASLOT + 8192;

    if (tid == 0) {
        #pragma unroll
        for (int s = 0; s < NST; s++)
            asm volatile("mbarrier.init.shared.b64 [%0], 1;"
                         :: "r"(smem_u32(&mb_full[s])) : "memory");
    }
    __syncthreads();

    auto arm = [&](int c) {
        int s = c % NST;
        uint32_t st = sb + s*STGB;
        uint32_t mb = smem_u32(&mb_full[s]);
        long o = (long)c * 8192;
        asm volatile("mbarrier.arrive.expect_tx.shared.b64 _, [%0], %1;"
                     :: "r"(mb), "r"((uint32_t)STGB) : "memory");
        asm volatile("cp.async.bulk.shared::cluster.global.mbarrier::complete_tx::bytes [%0], [%1], %2, [%3];"
                     :: "r"(st), "l"(pA0 + o), "r"((uint32_t)ASLOT), "r"(mb) : "memory");
        if (SPLIT)
            asm volatile("cp.async.bulk.shared::cluster.global.mbarrier::complete_tx::bytes [%0], [%1], %2, [%3];"
                         :: "r"(st + ASLOT), "l"(pA1 + o), "r"((uint32_t)ASLOT), "r"(mb) : "memory");
        asm volatile("cp.async.bulk.shared::cluster.global.mbarrier::complete_tx::bytes [%0], [%1], %2, [%3];"
                     :: "r"(st + NAB*ASLOT), "l"(pB + o), "r"(8192u), "r"(mb) : "memory");
    };
    constexpr int PRIME = (NC < NST) ? NC : NST;
    if (tid == 0) {
        #pragma unroll
        for (int c = 0; c < PRIME; c++) arm(c);
    }

    #pragma unroll
    for (int a=0;a<MI;a++)
        #pragma unroll
        for (int b2=0;b2<4;b2++)
            #pragma unroll
            for (int d=0;d<4;d++) acc[a][b2][d]=0.f;

    #pragma unroll 1
    for (int c = 0; c < NC; c++) {
        int s = c % NST;
        uint32_t par = (uint32_t)((c / NST) & 1);
        mbar_wait(smem_u32(&mb_full[s]), par);

        uint32_t st = sb + s*STGB;
        #pragma unroll
        for (int ks = 0; ks < 2; ks++) {
            uint32_t ah[MI][4], al[MI][4], bh[4][2];
            #pragma unroll
            for (int mi = 0; mi < MI; mi++) {
                int row = wm*(MI*16) + mi*16 + lr;
                int g = ks*2 + lh;
                uint32_t off = row*64 + ((g ^ ((row>>1)&3)) << 4);
                asm volatile("ldmatrix.sync.aligned.m8n8.x4.shared.b16 {%0,%1,%2,%3}, [%4];"
                    : "=r"(ah[mi][0]),"=r"(ah[mi][1]),"=r"(ah[mi][2]),"=r"(ah[mi][3])
                    : "r"(st + off));
                if (SPLIT)
                    asm volatile("ldmatrix.sync.aligned.m8n8.x4.shared.b16 {%0,%1,%2,%3}, [%4];"
                        : "=r"(al[mi][0]),"=r"(al[mi][1]),"=r"(al[mi][2]),"=r"(al[mi][3])
                        : "r"(st + ASLOT + off));
            }
            #pragma unroll
            for (int ni = 0; ni < 4; ni++) {
                int kr = ks*16 + lr;
                int gn = wn*4 + ni;
                uint32_t off = kr*256 + ((gn ^ (kr & 7)) << 4);
                asm volatile("ldmatrix.sync.aligned.m8n8.x2.trans.shared.b16 {%0,%1}, [%2];"
                    : "=r"(bh[ni][0]),"=r"(bh[ni][1]) : "r"(st + NAB*ASLOT + off));
            }
            #pragma unroll
            for (int mi = 0; mi < MI; mi++)
                #pragma unroll
                for (int ni = 0; ni < 4; ni++)
                    asm volatile("mma.sync.aligned.m16n8k16.row.col.f32.f16.f16.f32 "
                        "{%0,%1,%2,%3}, {%4,%5,%6,%7}, {%8,%9}, {%0,%1,%2,%3};"
                        : "+f"(acc[mi][ni][0]),"+f"(acc[mi][ni][1]),
                          "+f"(acc[mi][ni][2]),"+f"(acc[mi][ni][3])
                        : "r"(ah[mi][0]),"r"(ah[mi][1]),"r"(ah[mi][2]),"r"(ah[mi][3]),
                          "r"(bh[ni][0]),"r"(bh[ni][1]));
            if (SPLIT) {
                #pragma unroll
                for (int mi = 0; mi < MI; mi++)
                    #pragma unroll
                    for (int ni = 0; ni < 4; ni++)
                        asm volatile("mma.sync.aligned.m16n8k16.row.col.f32.f16.f16.f32 "
                            "{%0,%1,%2,%3}, {%4,%5,%6,%7}, {%8,%9}, {%0,%1,%2,%3};"
                            : "+f"(acc[mi][ni][0]),"+f"(acc[mi][ni][1]),
                              "+f"(acc[mi][ni][2]),"+f"(acc[mi][ni][3])
                            : "r"(al[mi][0]),"r"(al[mi][1]),"r"(al[mi][2]),"r"(al[mi][3]),
                              "r"(bh[ni][0]),"r"(bh[ni][1]));
            }
        }
        __syncthreads();
        if (tid == 0 && c + NST < NC) arm(c + NST);
    }
}

// ---------------- persistent big GEMM ----------------
template<int EPI, int SPLIT>
__global__ void __launch_bounds__(256, 2)
hgemm2p(const __half* __restrict__ Ahi, const __half* __restrict__ Alo,
        const __half* __restrict__ B, float* __restrict__ C, int N, int ctrIdx) {
    extern __shared__ __align__(1024) unsigned char sm[];
    __shared__ __align__(8) uint64_t mb_full[NST];
    __shared__ int s_tile;
    const int tid = threadIdx.x;
    const int lane = tid & 31, warp = tid >> 5;
    const int wm = warp >> 2, wn = warp & 3;
    const int lr = lane & 15, lh = lane >> 4;
    const int numTiles = (MR/128) * (N/128);
    const int rowTiles = MR/128;

    if (tid == 0) s_tile = atomicAdd(&g_ctr[ctrIdx], 1);
    __syncthreads();
    int tile = s_tile;

    while (tile < numTiles) {
        int by = tile % rowTiles;
        int bx = tile / rowTiles;
        int rowBase = by * 128, colBase = bx * 128;
        const char* pA0 = (const char*)Ahi + (long)(rowBase >> 7) * KCHUNKS * 8192;
        const char* pA1 = (const char*)Alo + (long)(rowBase >> 7) * KCHUNKS * 8192;
        const char* pB  = (const char*)B   + (long)(colBase >> 7) * KCHUNKS * 8192;
        float acc[4][4][4];
        gemm_core<4, KCHUNKS, SPLIT>(smem_u32(sm), mb_full, pA0, pA1, pB, tid, lr, lh, wm, wn, acc);
        #pragma unroll
        for (int mi = 0; mi < 4; mi++) {
            int r0 = rowBase + wm*64 + mi*16 + (lane >> 2);
            #pragma unroll
            for (int ni = 0; ni < 4; ni++) {
                int c0 = colBase + wn*32 + ni*8 + (lane & 3)*2;
                float2 v0, v1;
                v0.x = hepi<EPI>(acc[mi][ni][0]); v0.y = hepi<EPI>(acc[mi][ni][1]);
                v1.x = hepi<EPI>(acc[mi][ni][2]); v1.y = hepi<EPI>(acc[mi][ni][3]);
                *(float2*)&C[(long)r0*N + c0]     = v0;
                *(float2*)&C[(long)(r0+8)*N + c0] = v1;
            }
        }
        __syncthreads();
        if (tid == 0) s_tile = atomicAdd(&g_ctr[ctrIdx], 1);
        __syncthreads();
        tile = s_tile;
    }
}

// ---------------- tanh GEMM -> split-fp16 A-layout (mixt NCOUT=8, td NCOUT=4) ----------------
template<int MI, int NCOUT>
__global__ void __launch_bounds__(256, 2)
hgemm_tanh_split(const __half* __restrict__ Ahi, const __half* __restrict__ Alo,
                 const __half* __restrict__ B,
                 __half* __restrict__ Ohi, __half* __restrict__ Olo) {
    extern __shared__ __align__(1024) unsigned char sm[];
    __shared__ __align__(8) uint64_t mb_full[NST];
    const int tid = threadIdx.x;
    const int lane = tid & 31, warp = tid >> 5;
    const int wm = warp >> 2, wn = warp & 3;
    const int lr = lane & 15, lh = lane >> 4;
    const int rowBase = blockIdx.y * (MI*32), colBase = blockIdx.x * 128;
    const long aoff = (long)(rowBase >> 7) * KCHUNKS * 8192 + (long)((rowBase >> 5) & 3) * 2048;
    const char* pA0 = (const char*)Ahi + aoff;
    const char* pA1 = (const char*)Alo + aoff;
    const char* pB  = (const char*)B + (long)(colBase >> 7) * KCHUNKS * 8192;
    float acc[MI][4][4];
    gemm_core<MI, KCHUNKS, 1>(smem_u32(sm), mb_full, pA0, pA1, pB, tid, lr, lh, wm, wn, acc);
    #pragma unroll
    for (int mi = 0; mi < MI; mi++) {
        int r0 = rowBase + wm*(MI*16) + mi*16 + (lane >> 2);
        #pragma unroll
        for (int ni = 0; ni < 4; ni++) {
            int c0 = colBase + wn*32 + ni*8 + (lane & 3)*2;
            int e2 = (c0 & 7) * 2;
            long ba = a_tile_byte_k(r0,   c0 & ~7, NCOUT) + e2;
            long bb = a_tile_byte_k(r0+8, c0 & ~7, NCOUT) + e2;
            split2_store_h(tanhf(acc[mi][ni][0]), tanhf(acc[mi][ni][1]), (char*)Ohi, (char*)Olo, ba);
            split2_store_h(tanhf(acc[mi][ni][2]), tanhf(acc[mi][ni][3]), (char*)Ohi, (char*)Olo, bb);
        }
    }
}

// ---------------- mix GEMM (K=32, per-f) -> act_f split-fp16 A-layout ----------------
struct MixP { const float* maa[5]; };
__global__ void __launch_bounds__(256, 2)
hgemm_mix(const __half* __restrict__ Mhi, const __half* __restrict__ Mlo,
          const __half* __restrict__ W2, MixP mp,
          const float* __restrict__ x,
          __half* __restrict__ Ohi, __half* __restrict__ Olo) {
    extern __shared__ __align__(1024) unsigned char sm[];
    __shared__ __align__(8) uint64_t mb_full[NST];
    const int tid = threadIdx.x;
    const int lane = tid & 31, warp = tid >> 5;
    const int wm = warp >> 2, wn = warp & 3;
    const int lr = lane & 15, lh = lane >> 4;
    const int f = blockIdx.z;
    const int rowBase = blockIdx.y * 128, colBase = blockIdx.x * 128;
    const char* pA0 = (const char*)Mhi + ((long)(rowBase >> 7) * 8 + f) * 8192;
    const char* pA1 = (const char*)Mlo + ((long)(rowBase >> 7) * 8 + f) * 8192;
    const char* pB  = (const char*)W2 + (long)f*TMX*CC*2 + (long)(colBase >> 7) * 8192;
    float acc[4][4][4];
    gemm_core<4, 1, 1>(smem_u32(sm), mb_full, pA0, pA1, pB, tid, lr, lh, wm, wn, acc);

    const float* maa = mp.maa[f];
    char* oh = (char*)Ohi + (long)f*MR*CC*2;
    char* ol = (char*)Olo + (long)f*MR*CC*2;
    #pragma unroll
    for (int mi = 0; mi < 4; mi++) {
        int r0 = rowBase + wm*64 + mi*16 + (lane >> 2);
        int b0 = r0 / TT, b1 = (r0+8) / TT;
        #pragma unroll
        for (int ni = 0; ni < 4; ni++) {
            int c0 = colBase + wn*32 + ni*8 + (lane & 3)*2;
            float ma0 = maa[c0], ma1 = maa[c0+1];
            int e2 = (c0 & 7) * 2;
            {
                float xv0 = x[(long)r0*CC + c0], xv1 = x[(long)r0*CC + c0 + 1];
                float s0 = g_shift[b0*CC + c0], s1 = g_shift[b0*CC + c0 + 1];
                float v0 = xv0 + (s0 - xv0) * (ma0 + acc[mi][ni][0]);
                float v1 = xv1 + (s1 - xv1) * (ma1 + acc[mi][ni][1]);
                split2_store_h(v0, v1, oh, ol, a_tile_byte_k(r0, c0 & ~7, KCHUNKS) + e2);
            }
            {
                float xv0 = x[(long)(r0+8)*CC + c0], xv1 = x[(long)(r0+8)*CC + c0 + 1];
                float s0 = g_shift[b1*CC + c0], s1 = g_shift[b1*CC + c0 + 1];
                float v0 = xv0 + (s0 - xv0) * (ma0 + acc[mi][ni][2]);
                float v1 = xv1 + (s1 - xv1) * (ma1 + acc[mi][ni][3]);
                split2_store_h(v0, v1, oh, ol, a_tile_byte_k(r0+8, c0 & ~7, KCHUNKS) + e2);
            }
        }
    }
}

// ---------------- decay GEMM (K=128, NC=4): w = -exp(tdecay + td @ tdw2) ----------------
__global__ void __launch_bounds__(256, 2)
hgemm_decay(const __half* __restrict__ Ahi, const __half* __restrict__ Alo,
            const __half* __restrict__ B, const float* __restrict__ p1,
            float* __restrict__ C) {
    extern __shared__ __align__(1024) unsigned char sm[];
    __shared__ __align__(8) uint64_t mb_full[NST];
    const int tid = threadIdx.x;
    const int lane = tid & 31, warp = tid >> 5;
    const int wm = warp >> 2, wn = warp & 3;
    const int lr = lane & 15, lh = lane >> 4;
    const int rowBase = blockIdx.y * 128, colBase = blockIdx.x * 128;
    const char* pA0 = (const char*)Ahi + (long)(rowBase >> 7) * 4 * 8192;
    const char* pA1 = (const char*)Alo + (long)(rowBase >> 7) * 4 * 8192;
    const char* pB  = (const char*)B + (long)(colBase >> 7) * 4 * 8192;
    float acc[4][4][4];
    gemm_core<4, 4, 1>(smem_u32(sm), mb_full, pA0, pA1, pB, tid, lr, lh, wm, wn, acc);
    #pragma unroll
    for (int mi = 0; mi < 4; mi++) {
        int r0 = rowBase + wm*64 + mi*16 + (lane >> 2);
        #pragma unroll
        for (int ni = 0; ni < 4; ni++) {
            int c0 = colBase + wn*32 + ni*8 + (lane & 3)*2;
            float p0 = p1[c0], pp1 = p1[c0+1];
            float2 v0, v1;
            v0.x = -expf(p0  + acc[mi][ni][0]); v0.y = -expf(pp1 + acc[mi][ni][1]);
            v1.x = -expf(p0  + acc[mi][ni][2]); v1.y = -expf(pp1 + acc[mi][ni][3]);
            *(float2*)&C[(long)r0*AA + c0]     = v0;
            *(float2*)&C[(long)(r0+8)*AA + c0] = v1;
        }
    }
}

// ---------------- recurrence: split-K, 128 threads per (b,h) ----------------
__global__ void scan_kernel(const float* __restrict__ kv_state,
                            const float* __restrict__ faaaa) {
    int b = blockIdx.x / HH, h = blockIdx.x % HH;
    int tid = threadIdx.x;
    int half = tid >> 6;
    int v = tid & 63;
    __shared__ float r_sh[2][ZZ], k_sh[2][ZZ], ew_sh[2][ZZ], o_sh[2][ZZ];
    __shared__ float part[2][2];

    float S[32];
    const float* Sin = kv_state + ((long)(b*HH + h) * ZZ) * ZZ;
    #pragma unroll
    for (int j=0;j<32;j++) S[j] = Sin[(half*32+j)*ZZ + v];

    float uv = faaaa[h*ZZ + v];
    long base = (long)(b*TT) * AA + h*ZZ;
    float reset_b = g_reset[b];
    int lane = tid & 31, wrp = tid >> 5;

    float rv = 0.f, kvv = 0.f, wl = 0.f;
    float vv = g_v[base + v];
    if (half == 0) {
        rv  = g_r[base + v];
        kvv = g_k[base + v];
        wl  = g_w[base + v] + reset_b;
    }

    for (int t=0;t<TT;t++) {
        int bi = t & 1;
        if (half == 0) {
            r_sh[bi][v]  = rv;
            k_sh[bi][v]  = kvv;
            ew_sh[bi][v] = expf(wl);
            float p = rv * uv * kvv;
            #pragma unroll
            for (int off=16; off; off >>= 1) p += __shfl_xor_sync(0xffffffffu, p, off);
            if (lane == 0) part[bi][wrp] = p;
        }
        __syncthreads();

        float rv_n = 0.f, kv_n = 0.f, wl_n = 0.f, vv_n = 0.f;
        if (t + 1 < TT) {
            long nb = base + (long)(t+1)*AA;
            vv_n = g_v[nb + v];
            if (half == 0) {
                rv_n = g_r[nb + v];
                kv_n = g_k[nb + v];
                wl_n = g_w[nb + v];
            }
        }

        float ruk = part[bi][0] + part[bi][1];
        const float* rs  = r_sh[bi]  + half*32;
        const float* ks  = k_sh[bi]  + half*32;
        const float* ews = ew_sh[bi] + half*32;
        float o0 = 0.f, o1 = 0.f, o2 = 0.f, o3 = 0.f;
        #pragma unroll
        for (int j=0;j<32;j+=4) {
            o0 = fmaf(rs[j],   S[j],   o0); S[j]   = fmaf(ews[j],   S[j],   ks[j]*vv);
            o1 = fmaf(rs[j+1], S[j+1], o1); S[j+1] = fmaf(ews[j+1], S[j+1], ks[j+1]*vv);
            o2 = fmaf(rs[j+2], S[j+2], o2); S[j+2] = fmaf(ews[j+2], S[j+2], ks[j+2]*vv);
            o3 = fmaf(rs[j+3], S[j+3], o3); S[j+3] = fmaf(ews[j+3], S[j+3], ks[j+3]*vv);
        }
        float o = (o0 + o1) + (o2 + o3);
        if (half == 1) o_sh[bi][v] = o;
        __syncthreads();
        if (half == 0)
            g_xo[base + (long)t*AA + v] = o + o_sh[bi][v] + ruk * vv;

        rv = rv_n; kvv = kv_n; wl = wl_n; vv = vv_n;
    }
}

// ---------------- groupnorm + gate -> tiled A-layout (fp16 split) ----------------
__global__ void gn_gate_kernel(const float* __restrict__ ln_w,
                               const float* __restrict__ ln_b) {
    int gid = blockIdx.x * (blockDim.x >> 5) + (threadIdx.x >> 5);
    int lane = threadIdx.x & 31;
    if (gid >= MR*HH) return;
    int bt = gid / HH, h = gid % HH;
    long base = (long)bt*CC + h*ZZ;
    float x0 = g_xo[base + lane];
    float x1 = g_xo[base + lane + 32];
    float s = x0 + x1;
    #pragma unroll
    for (int off=16; off; off >>= 1) s += __shfl_xor_sync(0xffffffffu, s, off);
    float mu = s * (1.0f/64.0f);
    float d0 = x0 - mu, d1 = x1 - mu;
    float q = d0*d0 + d1*d1;
    #pragma unroll
    for (int off=16; off; off >>= 1) q += __shfl_xor_sync(0xffffffffu, q, off);
    float rs = rsqrtf(q * (1.0f/64.0f) + EPS_GN);
    int c0 = h*ZZ + lane, c1 = c0 + 32;
    float g0 = (d0 * rs * ln_w[c0] + ln_b[c0]) * g_gate[base + lane];
    float g1 = (d1 * rs * ln_w[c1] + ln_b[c1]) * g_gate[base + lane + 32];
    long b0 = a_tile_byte(bt, c0 & ~7) + (c0 & 7)*2;
    long b1 = a_tile_byte(bt, c1 & ~7) + (c1 & 7)*2;
    __half h0 = __float2half_rn(g0);
    __half h1 = __float2half_rn(g1);
    *(__half*)((char*)g_g_hi + b0) = h0;
    *(__half*)((char*)g_g_lo + b0) = __float2half_rn(g0 - __half2float(h0));
    *(__half*)((char*)g_g_hi + b1) = h1;
    *(__half*)((char*)g_g_lo + b1) = __float2half_rn(g1 - __half2float(h1));
}

// ---------------- launch ----------------
extern "C" void kernel_launch(void* const* d_in, const int* in_sizes, int n_in,
                              void* d_out, int out_size) {
    const float* x        = (const float*)d_in[0];
    const int*   pos      = (const int*)  d_in[1];
    const float* kv_state = (const float*)d_in[2];
    const float* shift_st = (const float*)d_in[3];
    const float* maa_x    = (const float*)d_in[4];
    const float* maa_f[5] = { (const float*)d_in[5], (const float*)d_in[6],
                              (const float*)d_in[7], (const float*)d_in[8],
                              (const float*)d_in[9] };       // w,k,v,r,g
    const float* w1       = (const float*)d_in[10];
    const float* w2       = (const float*)d_in[11];
    const float* tdecay   = (const float*)d_in[12];
    const float* tdw1     = (const float*)d_in[13];
    const float* tdw2     = (const float*)d_in[14];
    const float* faaaa    = (const float*)d_in[15];
    const float* Wmat[5]  = { (const float*)d_in[16], (const float*)d_in[17],
                              (const float*)d_in[18], (const float*)d_in[19],
                              (const float*)d_in[20] };      // W_r,W_k,W_v,W_g,W_o
    const float* ln_w     = (const float*)d_in[21];
    const float* ln_b     = (const float*)d_in[22];
    float* out = (float*)d_out;

    float *rb, *kb, *vb, *gateb, *wb;
    __half *xxh, *xxl, *w1h, *tdh, *Wh, *ah, *al, *gh, *gl;
    __half *mth, *mtl, *tdsh, *tdsl, *w2h, *tdw2h;
    cudaGetSymbolAddress((void**)&rb,   g_r);
    cudaGetSymbolAddress((void**)&kb,   g_k);
    cudaGetSymbolAddress((void**)&vb,   g_v);
    cudaGetSymbolAddress((void**)&gateb,g_gate);
    cudaGetSymbolAddress((void**)&wb,   g_w);
    cudaGetSymbolAddress((void**)&xxh,  g_xxx_hi);
    cudaGetSymbolAddress((void**)&xxl,  g_xxx_lo);
    cudaGetSymbolAddress((void**)&w1h,  g_w1_h);
    cudaGetSymbolAddress((void**)&tdh,  g_tdw1_h);
    cudaGetSymbolAddress((void**)&Wh,   g_W_h);
    cudaGetSymbolAddress((void**)&ah,   g_act_hi);
    cudaGetSymbolAddress((void**)&al,   g_act_lo);
    cudaGetSymbolAddress((void**)&gh,   g_g_hi);
    cudaGetSymbolAddress((void**)&gl,   g_g_lo);
    cudaGetSymbolAddress((void**)&mth,  g_mixt_hi);
    cudaGetSymbolAddress((void**)&mtl,  g_mixt_lo);
    cudaGetSymbolAddress((void**)&tdsh, g_td_hi);
    cudaGetSymbolAddress((void**)&tdsl, g_td_lo);
    cudaGetSymbolAddress((void**)&w2h,  g_w2_h);
    cudaGetSymbolAddress((void**)&tdw2h,g_tdw2_h);

    const int SM128  = 3 * (2*8192 + 8192);     // split MI=4: 73728
    const int SM128S = 3 * (8192 + 8192);       // single MI=4: 49152
    const int SM64   = 3 * (2*4096 + 8192);     // split MI=2: 49152
    const int SMMIX  = (2*8192 + 8192);         // 24576
    cudaFuncSetAttribute((const void*)hgemm2p<0,1>,         cudaFuncAttributeMaxDynamicSharedMemorySize, SM128);
    cudaFuncSetAttribute((const void*)hgemm2p<2,0>,         cudaFuncAttributeMaxDynamicSharedMemorySize, SM128S);
    cudaFuncSetAttribute((const void*)hgemm_tanh_split<2,8>,cudaFuncAttributeMaxDynamicSharedMemorySize, SM64);
    cudaFuncSetAttribute((const void*)hgemm_tanh_split<2,4>,cudaFuncAttributeMaxDynamicSharedMemorySize, SM64);
    cudaFuncSetAttribute((const void*)hgemm_mix,            cudaFuncAttributeMaxDynamicSharedMemorySize, SMMIX);
    cudaFuncSetAttribute((const void*)hgemm_decay,          cudaFuncAttributeMaxDynamicSharedMemorySize, SM128);

    const long WC = (long)CC * AA;
    MixP mp; for (int i=0;i<5;i++) mp.maa[i] = maa_f[i];
    W5 w5; for (int i=0;i<5;i++) w5.p[i] = Wmat[i];

    // ---- fork: weight packs on side stream ----
    cudaStream_t s2;
    cudaStreamCreate(&s2);
    cudaEvent_t eFork, eJoin, eAct, eGate;
    cudaEventCreate(&eFork);
    cudaEventCreate(&eJoin);
    cudaEventCreate(&eAct);
    cudaEventCreate(&eGate);
    cudaEventRecord(eFork, 0);
    cudaStreamWaitEvent(s2, eFork, 0);
    pack5_kernel<<<(5*KDIM*(AA/8) + 255)/256, 256, 0, s2>>>(w5, Wh);
    padsplit_kernel<<<(KDIM*(NTD/8) + 255)/256, 256, 0, s2>>>(tdw1, tdh, TDX, NTD);
    pack_tdw2_kernel<<<(NTD*(AA/8) + 255)/256, 256, 0, s2>>>(tdw2, tdw2h);
    cudaEventRecord(eJoin, s2);

    // main: activation chain
    mixx_kernel<<<(MR*CC/8 + 255)/256, 256>>>(x, maa_x, pos, shift_st);
    padsplit_kernel<<<(KDIM*(NMIX/8) + 255)/256, 256>>>(w1, w1h, 5*TMX, NMIX);
    hgemm_tanh_split<2,8><<<dim3(NMIX/128, MR/64), 256, SM64>>>(xxh, xxl, w1h, mth, mtl);
    pack_w2_kernel<<<(5*TMX*(CC/8) + 255)/256, 256>>>(w2, w2h);
    hgemm_mix<<<dim3(CC/128, MR/128, 5), 256, SMMIX>>>(mth, mtl, w2h, mp, x, ah, al);
    cudaEventRecord(eAct, 0);
    cudaStreamWaitEvent(0, eJoin, 0);

    // side stream: gate projection (single-pass A) overlapping td/decay/scan
    cudaStreamWaitEvent(s2, eAct, 0);
    hgemm2p<2,0><<<PGRID, 256, SM128S, s2>>>(ah + 4L*MR*CC, al, Wh + 3*WC, gateb, AA, 3);
    cudaEventRecord(eGate, s2);

    // main: r, k, v projections (split)
    hgemm2p<0,1><<<PGRID, 256, SM128>>>(ah + 3L*MR*CC, al + 3L*MR*CC, Wh + 0*WC, rb, AA, 0);
    hgemm2p<0,1><<<PGRID, 256, SM128>>>(ah + 1L*MR*CC, al + 1L*MR*CC, Wh + 1*WC, kb, AA, 1);
    hgemm2p<0,1><<<PGRID, 256, SM128>>>(ah + 2L*MR*CC, al + 2L*MR*CC, Wh + 2*WC, vb, AA, 2);
    // td + decay + scan
    hgemm_tanh_split<2,4><<<dim3(NTD/128, MR/64), 256, SM64>>>(ah, al, tdh, tdsh, tdsl);
    hgemm_decay<<<dim3(AA/128, MR/128), 256, SM128>>>(tdsh, tdsl, tdw2h, tdecay, wb);
    scan_kernel<<<BB*HH, 128>>>(kv_state, faaaa);
    // join gate, then groupnorm + out projection
    cudaStreamWaitEvent(0, eGate, 0);
    gn_gate_kernel<<<(MR*HH + 7)/8, 256>>>(ln_w, ln_b);
    hgemm2p<0,1><<<PGRID, 256, SM128>>>(gh, gl, Wh + 4*WC, out, CC, 4);
}

// round 16
// speedup vs baseline: 1.0975x; 1.0164x over previous
#include <cuda_runtime.h>
#include <cuda_fp16.h>
#include <math.h>
#include <stdint.h>

// ---------------- problem dims ----------------
#define BB   8
#define TT   512
#define CC   2048
#define HH   32
#define ZZ   64
#define AA   2048
#define MR   (BB*TT)         // 4096
#define TMX  32
#define TDX  64
#define NMIX 256
#define NTD  128
#define EPS_GN (1e-5f * 64.0f)

#define KDIM    2048
#define KCHUNKS 64
#define NST     3
#define PGRID   296

// ---------------- scratch ----------------
__device__ float g_shift[BB*CC];
__device__ float g_reset[BB];
__device__ int   g_ctr[8];
__device__ __align__(1024) __half g_xxx_hi[MR*CC];
__device__ __align__(1024) __half g_xxx_lo[MR*CC];
__device__ __align__(1024) __half g_act_hi[5u*MR*CC];
__device__ __align__(1024) __half g_act_lo[5u*MR*CC];
__device__ __align__(1024) __half g_g_hi[MR*AA];
__device__ __align__(1024) __half g_g_lo[MR*AA];
__device__ __align__(1024) __half g_mixt_hi[MR*NMIX];
__device__ __align__(1024) __half g_mixt_lo[MR*NMIX];
__device__ __align__(1024) __half g_td_hi[MR*NTD];
__device__ __align__(1024) __half g_td_lo[MR*NTD];
__device__ __align__(1024) __half g_w1_h[CC*NMIX];
__device__ __align__(1024) __half g_tdw1_h[CC*NTD];
__device__ __align__(1024) __half g_W_h[5u*CC*AA];
__device__ __align__(1024) __half g_w2_h[5u*TMX*CC];
__device__ __align__(1024) __half g_tdw2_h[NTD*AA];
__device__ float g_r[MR*AA];
__device__ float g_k[MR*AA];
__device__ float g_v[MR*AA];
__device__ float g_gate[MR*AA];
__device__ float g_w[MR*AA];
__device__ float g_xo[MR*AA];

// ---------------- helpers ----------------
__device__ __forceinline__ uint32_t smem_u32(const void* p) {
    return (uint32_t)__cvta_generic_to_shared(p);
}
template<int EPI>
__device__ __forceinline__ float hepi(float a) {
    if (EPI == 2) return a / (1.0f + expf(-a));
    return a;
}
__device__ __forceinline__ void mbar_wait(uint32_t mb, uint32_t parity) {
    asm volatile(
        "{\n\t.reg .pred P;\n\t"
        "WL%=:\n\t"
        "mbarrier.try_wait.parity.shared.b64 P, [%0], %1;\n\t"
        "@P bra WD%=;\n\t"
        "bra WL%=;\n\t"
        "WD%=:\n\t}"
        :: "r"(mb), "r"(parity) : "memory");
}
__device__ __forceinline__ long a_tile_byte_k(int m, int k0, int nc) {
    int r = m & 127, g = (k0 & 31) >> 3;
    return ((long)((m >> 7) * nc + (k0 >> 5))) * 8192 + r*64 + ((g ^ ((r>>1)&3)) << 4);
}
__device__ __forceinline__ long b_tile_byte_k(int k, int n0, int nc) {
    int kr = k & 31, gn = (n0 & 127) >> 3;
    return ((long)((n0 >> 7) * nc + (k >> 5))) * 8192 + kr*256 + ((gn ^ (kr&7)) << 4);
}
__device__ __forceinline__ long a_tile_byte(int m, int k0) { return a_tile_byte_k(m, k0, KCHUNKS); }
__device__ __forceinline__ long b_tile_byte(int k, int n0) { return b_tile_byte_k(k, n0, KCHUNKS); }

__device__ __forceinline__ void split8_store_h(const float* v, char* hi, char* lo, long byte) {
    uint32_t ph[4], pl[4];
    #pragma unroll
    for (int j = 0; j < 4; j++) {
        __half h0 = __float2half_rn(v[2*j]);
        __half h1 = __float2half_rn(v[2*j+1]);
        float l0 = v[2*j]   - __half2float(h0);
        float l1 = v[2*j+1] - __half2float(h1);
        __half2 hh; hh.x = h0; hh.y = h1;
        __half2 ll; ll.x = __float2half_rn(l0); ll.y = __float2half_rn(l1);
        ph[j] = *(uint32_t*)&hh; pl[j] = *(uint32_t*)&ll;
    }
    *(uint4*)(hi + byte) = make_uint4(ph[0], ph[1], ph[2], ph[3]);
    *(uint4*)(lo + byte) = make_uint4(pl[0], pl[1], pl[2], pl[3]);
}
__device__ __forceinline__ void pack8_store_h(const float* v, char* dst, long byte) {
    uint32_t p[4];
    #pragma unroll
    for (int j = 0; j < 4; j++) {
        __half2 hh; hh.x = __float2half_rn(v[2*j]); hh.y = __float2half_rn(v[2*j+1]);
        p[j] = *(uint32_t*)&hh;
    }
    *(uint4*)(dst + byte) = make_uint4(p[0], p[1], p[2], p[3]);
}
__device__ __forceinline__ void split2_store_h(float v0, float v1, char* hi, char* lo, long byte) {
    __half h0 = __float2half_rn(v0), h1 = __float2half_rn(v1);
    __half2 hh; hh.x = h0; hh.y = h1;
    __half2 ll; ll.x = __float2half_rn(v0 - __half2float(h0));
    ll.y = __float2half_rn(v1 - __half2float(h1));
    *(__half2*)(hi + byte) = hh;
    *(__half2*)(lo + byte) = ll;
}

// ---------------- fused prep + xxx (also resets tile counters) ----------------
__global__ void mixx_kernel(const float* __restrict__ x,
                            const float* __restrict__ maa_x,
                            const int* __restrict__ positions,
                            const float* __restrict__ shift_state) {
    int idx = blockIdx.x * blockDim.x + threadIdx.x;
    if (idx < 8) g_ctr[idx] = 0;
    if (idx >= MR*CC/8) return;
    int m  = idx >> 8;
    int k0 = (idx & 255) << 3;
    int b  = m / TT;
    float rst = (positions[b*TT] == 0) ? -100.0f : 0.0f;
    float erst = expf(rst);
    float v[8];
    #pragma unroll
    for (int e = 0; e < 8; e++) {
        int c = k0 + e;
        float sh = shift_state[b*CC + c] * erst;
        if ((m % TT) == 0) g_shift[b*CC + c] = sh;
        float xv = x[(long)m*CC + c];
        v[e] = xv + (sh - xv) * maa_x[c];
    }
    if ((m % TT) == 0 && k0 == 0) g_reset[b] = rst;
    split8_store_h(v, (char*)g_xxx_hi, (char*)g_xxx_lo, a_tile_byte(m, k0));
}

// ---------------- pad fp32 [K=2048,Nsrc] -> fp16 tiled B-layout ----------------
__global__ void padsplit_kernel(const float* __restrict__ src,
                                __half* __restrict__ dst,
                                int Nsrc, int Ndst) {
    int idx = blockIdx.x * blockDim.x + threadIdx.x;
    int gpr = Ndst >> 3;
    if (idx >= KDIM*gpr) return;
    int k  = idx / gpr;
    int n0 = (idx % gpr) << 3;
    float v[8];
    #pragma unroll
    for (int e = 0; e < 8; e++) {
        int n = n0 + e;
        v[e] = (n < Nsrc) ? src[(long)k*Nsrc + n] : 0.0f;
    }
    pack8_store_h(v, (char*)dst, b_tile_byte(k, n0));
}

// ---------------- fused pack of all five [2048,2048] weights ----------------
struct W5 { const float* p[5]; };
__global__ void pack5_kernel(W5 w, __half* __restrict__ dst) {
    int idx = blockIdx.x * blockDim.x + threadIdx.x;
    const int per_f = KDIM * (AA/8);
    if (idx >= 5*per_f) return;
    int f = idx / per_f, rem = idx % per_f;
    int k = rem / (AA/8);
    int n0 = (rem % (AA/8)) << 3;
    const float* src = w.p[f];
    float v[8];
    #pragma unroll
    for (int e = 0; e < 8; e++) v[e] = src[(long)k*AA + n0 + e];
    pack8_store_h(v, (char*)dst + (long)f*CC*AA*2, b_tile_byte(k, n0));
}

// ---------------- pack w2 [5,32,CC] -> 5 x B-layout (kc=1) ----------------
__global__ void pack_w2_kernel(const float* __restrict__ w2, __half* __restrict__ dst) {
    int idx = blockIdx.x * blockDim.x + threadIdx.x;
    const int per_f = TMX * (CC/8);
    if (idx >= 5*per_f) return;
    int f = idx / per_f, rem = idx % per_f;
    int k = rem / (CC/8);
    int n0 = (rem % (CC/8)) << 3;
    float v[8];
    #pragma unroll
    for (int e = 0; e < 8; e++) v[e] = w2[(long)f*TMX*CC + (long)k*CC + n0 + e];
    pack8_store_h(v, (char*)dst + (long)f*TMX*CC*2, b_tile_byte_k(k, n0, 1));
}

// ---------------- pack tdw2 [64,AA] -> B-layout K padded to 128 (kc=4) ----------------
__global__ void pack_tdw2_kernel(const float* __restrict__ tdw2, __half* __restrict__ dst) {
    int idx = blockIdx.x * blockDim.x + threadIdx.x;
    if (idx >= NTD*(AA/8)) return;
    int k = idx / (AA/8);
    int n0 = (idx % (AA/8)) << 3;
    float v[8];
    #pragma unroll
    for (int e = 0; e < 8; e++) v[e] = (k < TDX) ? tdw2[(long)k*AA + n0 + e] : 0.0f;
    pack8_store_h(v, (char*)dst, b_tile_byte_k(k, n0, 4));
}

// ---------------- core GEMM: MI*32 x 128 tile, NC K-chunks, SPLIT=1 -> hi+lo A ----------------
template<int MI, int NC, int SPLIT>
__device__ __forceinline__ void gemm_core(
        uint32_t sb, uint64_t* mb_full,
        const char* pA0, const char* pA1, const char* pB,
        int tid, int lr, int lh, int wm, int wn,
        float acc[MI][4][4]) {
    constexpr int ASLOT = MI * 2048;
    constexpr int NAB   = SPLIT ? 2 : 1;
    constexpr int STGB  = NAB*ASLOT + 8192;

    if (tid == 0) {
        #pragma unroll
        for (int s = 0; s < NST; s++)
            asm volatile("mbarrier.init.shared.b64 [%0], 1;"
                         :: "r"(smem_u32(&mb_full[s])) : "memory");
    }
    __syncthreads();

    auto arm = [&](int c) {
        int s = c % NST;
        uint32_t st = sb + s*STGB;
        uint32_t mb = smem_u32(&mb_full[s]);
        long o = (long)c * 8192;
        asm volatile("mbarrier.arrive.expect_tx.shared.b64 _, [%0], %1;"
                     :: "r"(mb), "r"((uint32_t)STGB) : "memory");
        asm volatile("cp.async.bulk.shared::cluster.global.mbarrier::complete_tx::bytes [%0], [%1], %2, [%3];"
                     :: "r"(st), "l"(pA0 + o), "r"((uint32_t)ASLOT), "r"(mb) : "memory");
        if (SPLIT)
            asm volatile("cp.async.bulk.shared::cluster.global.mbarrier::complete_tx::bytes [%0], [%1], %2, [%3];"
                         :: "r"(st + ASLOT), "l"(pA1 + o), "r"((uint32_t)ASLOT), "r"(mb) : "memory");
        asm volatile("cp.async.bulk.shared::cluster.global.mbarrier::complete_tx::bytes [%0], [%1], %2, [%3];"
                     :: "r"(st + NAB*ASLOT), "l"(pB + o), "r"(8192u), "r"(mb) : "memory");
    };
    constexpr int PRIME = (NC < NST) ? NC : NST;
    if (tid == 0) {
        #pragma unroll
        for (int c = 0; c < PRIME; c++) arm(c);
    }

    #pragma unroll
    for (int a=0;a<MI;a++)
        #pragma unroll
        for (int b2=0;b2<4;b2++)
            #pragma unroll
            for (int d=0;d<4;d++) acc[a][b2][d]=0.f;

    #pragma unroll 1
    for (int c = 0; c < NC; c++) {
        int s = c % NST;
        uint32_t par = (uint32_t)((c / NST) & 1);
        mbar_wait(smem_u32(&mb_full[s]), par);

        uint32_t st = sb + s*STGB;
        #pragma unroll
        for (int ks = 0; ks < 2; ks++) {
            uint32_t ah[MI][4], al[MI][4], bh[4][2];
            #pragma unroll
            for (int mi = 0; mi < MI; mi++) {
                int row = wm*(MI*16) + mi*16 + lr;
                int g = ks*2 + lh;
                uint32_t off = row*64 + ((g ^ ((row>>1)&3)) << 4);
                asm volatile("ldmatrix.sync.aligned.m8n8.x4.shared.b16 {%0,%1,%2,%3}, [%4];"
                    : "=r"(ah[mi][0]),"=r"(ah[mi][1]),"=r"(ah[mi][2]),"=r"(ah[mi][3])
                    : "r"(st + off));
                if (SPLIT)
                    asm volatile("ldmatrix.sync.aligned.m8n8.x4.shared.b16 {%0,%1,%2,%3}, [%4];"
                        : "=r"(al[mi][0]),"=r"(al[mi][1]),"=r"(al[mi][2]),"=r"(al[mi][3])
                        : "r"(st + ASLOT + off));
            }
            #pragma unroll
            for (int ni = 0; ni < 4; ni++) {
                int kr = ks*16 + lr;
                int gn = wn*4 + ni;
                uint32_t off = kr*256 + ((gn ^ (kr & 7)) << 4);
                asm volatile("ldmatrix.sync.aligned.m8n8.x2.trans.shared.b16 {%0,%1}, [%2];"
                    : "=r"(bh[ni][0]),"=r"(bh[ni][1]) : "r"(st + NAB*ASLOT + off));
            }
            #pragma unroll
            for (int mi = 0; mi < MI; mi++)
                #pragma unroll
                for (int ni = 0; ni < 4; ni++)
                    asm volatile("mma.sync.aligned.m16n8k16.row.col.f32.f16.f16.f32 "
                        "{%0,%1,%2,%3}, {%4,%5,%6,%7}, {%8,%9}, {%0,%1,%2,%3};"
                        : "+f"(acc[mi][ni][0]),"+f"(acc[mi][ni][1]),
                          "+f"(acc[mi][ni][2]),"+f"(acc[mi][ni][3])
                        : "r"(ah[mi][0]),"r"(ah[mi][1]),"r"(ah[mi][2]),"r"(ah[mi][3]),
                          "r"(bh[ni][0]),"r"(bh[ni][1]));
            if (SPLIT) {
                #pragma unroll
                for (int mi = 0; mi < MI; mi++)
                    #pragma unroll
                    for (int ni = 0; ni < 4; ni++)
                        asm volatile("mma.sync.aligned.m16n8k16.row.col.f32.f16.f16.f32 "
                            "{%0,%1,%2,%3}, {%4,%5,%6,%7}, {%8,%9}, {%0,%1,%2,%3};"
                            : "+f"(acc[mi][ni][0]),"+f"(acc[mi][ni][1]),
                              "+f"(acc[mi][ni][2]),"+f"(acc[mi][ni][3])
                            : "r"(al[mi][0]),"r"(al[mi][1]),"r"(al[mi][2]),"r"(al[mi][3]),
                              "r"(bh[ni][0]),"r"(bh[ni][1]));
            }
        }
        __syncthreads();
        if (tid == 0 && c + NST < NC) arm(c + NST);
    }
}

// ---------------- persistent big GEMM ----------------
template<int EPI, int SPLIT>
__global__ void __launch_bounds__(256, 2)
hgemm2p(const __half* __restrict__ Ahi, const __half* __restrict__ Alo,
        const __half* __restrict__ B, float* __restrict__ C, int N, int ctrIdx) {
    extern __shared__ __align__(1024) unsigned char sm[];
    __shared__ __align__(8) uint64_t mb_full[NST];
    __shared__ int s_tile;
    const int tid = threadIdx.x;
    const int lane = tid & 31, warp = tid >> 5;
    const int wm = warp >> 2, wn = warp & 3;
    const int lr = lane & 15, lh = lane >> 4;
    const int numTiles = (MR/128) * (N/128);
    const int rowTiles = MR/128;

    if (tid == 0) s_tile = atomicAdd(&g_ctr[ctrIdx], 1);
    __syncthreads();
    int tile = s_tile;

    while (tile < numTiles) {
        int by = tile % rowTiles;
        int bx = tile / rowTiles;
        int rowBase = by * 128, colBase = bx * 128;
        const char* pA0 = (const char*)Ahi + (long)(rowBase >> 7) * KCHUNKS * 8192;
        const char* pA1 = (const char*)Alo + (long)(rowBase >> 7) * KCHUNKS * 8192;
        const char* pB  = (const char*)B   + (long)(colBase >> 7) * KCHUNKS * 8192;
        float acc[4][4][4];
        gemm_core<4, KCHUNKS, SPLIT>(smem_u32(sm), mb_full, pA0, pA1, pB, tid, lr, lh, wm, wn, acc);
        #pragma unroll
        for (int mi = 0; mi < 4; mi++) {
            int r0 = rowBase + wm*64 + mi*16 + (lane >> 2);
            #pragma unroll
            for (int ni = 0; ni < 4; ni++) {
                int c0 = colBase + wn*32 + ni*8 + (lane & 3)*2;
                float2 v0, v1;
                v0.x = hepi<EPI>(acc[mi][ni][0]); v0.y = hepi<EPI>(acc[mi][ni][1]);
                v1.x = hepi<EPI>(acc[mi][ni][2]); v1.y = hepi<EPI>(acc[mi][ni][3]);
                *(float2*)&C[(long)r0*N + c0]     = v0;
                *(float2*)&C[(long)(r0+8)*N + c0] = v1;
            }
        }
        __syncthreads();
        if (tid == 0) s_tile = atomicAdd(&g_ctr[ctrIdx], 1);
        __syncthreads();
        tile = s_tile;
    }
}

// ---------------- tanh GEMM -> split-fp16 A-layout (mixt NCOUT=8, td NCOUT=4) ----------------
template<int MI, int NCOUT>
__global__ void __launch_bounds__(256, 2)
hgemm_tanh_split(const __half* __restrict__ Ahi, const __half* __restrict__ Alo,
                 const __half* __restrict__ B,
                 __half* __restrict__ Ohi, __half* __restrict__ Olo) {
    extern __shared__ __align__(1024) unsigned char sm[];
    __shared__ __align__(8) uint64_t mb_full[NST];
    const int tid = threadIdx.x;
    const int lane = tid & 31, warp = tid >> 5;
    const int wm = warp >> 2, wn = warp & 3;
    const int lr = lane & 15, lh = lane >> 4;
    const int rowBase = blockIdx.y * (MI*32), colBase = blockIdx.x * 128;
    const long aoff = (long)(rowBase >> 7) * KCHUNKS * 8192 + (long)((rowBase >> 5) & 3) * 2048;
    const char* pA0 = (const char*)Ahi + aoff;
    const char* pA1 = (const char*)Alo + aoff;
    const char* pB  = (const char*)B + (long)(colBase >> 7) * KCHUNKS * 8192;
    float acc[MI][4][4];
    gemm_core<MI, KCHUNKS, 1>(smem_u32(sm), mb_full, pA0, pA1, pB, tid, lr, lh, wm, wn, acc);
    #pragma unroll
    for (int mi = 0; mi < MI; mi++) {
        int r0 = rowBase + wm*(MI*16) + mi*16 + (lane >> 2);
        #pragma unroll
        for (int ni = 0; ni < 4; ni++) {
            int c0 = colBase + wn*32 + ni*8 + (lane & 3)*2;
            int e2 = (c0 & 7) * 2;
            long ba = a_tile_byte_k(r0,   c0 & ~7, NCOUT) + e2;
            long bb = a_tile_byte_k(r0+8, c0 & ~7, NCOUT) + e2;
            split2_store_h(tanhf(acc[mi][ni][0]), tanhf(acc[mi][ni][1]), (char*)Ohi, (char*)Olo, ba);
            split2_store_h(tanhf(acc[mi][ni][2]), tanhf(acc[mi][ni][3]), (char*)Ohi, (char*)Olo, bb);
        }
    }
}

// ---------------- mix GEMM (K=32, per-f) -> act_f split-fp16 A-layout ----------------
struct MixP { const float* maa[5]; };
__global__ void __launch_bounds__(256, 2)
hgemm_mix(const __half* __restrict__ Mhi, const __half* __restrict__ Mlo,
          const __half* __restrict__ W2, MixP mp,
          const float* __restrict__ x,
          __half* __restrict__ Ohi, __half* __restrict__ Olo) {
    extern __shared__ __align__(1024) unsigned char sm[];
    __shared__ __align__(8) uint64_t mb_full[NST];
    const int tid = threadIdx.x;
    const int lane = tid & 31, warp = tid >> 5;
    const int wm = warp >> 2, wn = warp & 3;
    const int lr = lane & 15, lh = lane >> 4;
    const int f = blockIdx.z;
    const int rowBase = blockIdx.y * 128, colBase = blockIdx.x * 128;
    const char* pA0 = (const char*)Mhi + ((long)(rowBase >> 7) * 8 + f) * 8192;
    const char* pA1 = (const char*)Mlo + ((long)(rowBase >> 7) * 8 + f) * 8192;
    const char* pB  = (const char*)W2 + (long)f*TMX*CC*2 + (long)(colBase >> 7) * 8192;
    float acc[4][4][4];
    gemm_core<4, 1, 1>(smem_u32(sm), mb_full, pA0, pA1, pB, tid, lr, lh, wm, wn, acc);

    const float* maa = mp.maa[f];
    char* oh = (char*)Ohi + (long)f*MR*CC*2;
    char* ol = (char*)Olo + (long)f*MR*CC*2;
    #pragma unroll
    for (int mi = 0; mi < 4; mi++) {
        int r0 = rowBase + wm*64 + mi*16 + (lane >> 2);
        int b0 = r0 / TT, b1 = (r0+8) / TT;
        #pragma unroll
        for (int ni = 0; ni < 4; ni++) {
            int c0 = colBase + wn*32 + ni*8 + (lane & 3)*2;
            float ma0 = maa[c0], ma1 = maa[c0+1];
            int e2 = (c0 & 7) * 2;
            {
                float xv0 = x[(long)r0*CC + c0], xv1 = x[(long)r0*CC + c0 + 1];
                float s0 = g_shift[b0*CC + c0], s1 = g_shift[b0*CC + c0 + 1];
                float v0 = xv0 + (s0 - xv0) * (ma0 + acc[mi][ni][0]);
                float v1 = xv1 + (s1 - xv1) * (ma1 + acc[mi][ni][1]);
                split2_store_h(v0, v1, oh, ol, a_tile_byte_k(r0, c0 & ~7, KCHUNKS) + e2);
            }
            {
                float xv0 = x[(long)(r0+8)*CC + c0], xv1 = x[(long)(r0+8)*CC + c0 + 1];
                float s0 = g_shift[b1*CC + c0], s1 = g_shift[b1*CC + c0 + 1];
                float v0 = xv0 + (s0 - xv0) * (ma0 + acc[mi][ni][2]);
                float v1 = xv1 + (s1 - xv1) * (ma1 + acc[mi][ni][3]);
                split2_store_h(v0, v1, oh, ol, a_tile_byte_k(r0+8, c0 & ~7, KCHUNKS) + e2);
            }
        }
    }
}

// ---------------- decay GEMM (K=128, NC=4): w = -exp(tdecay + td @ tdw2) ----------------
__global__ void __launch_bounds__(256, 2)
hgemm_decay(const __half* __restrict__ Ahi, const __half* __restrict__ Alo,
            const __half* __restrict__ B, const float* __restrict__ p1,
            float* __restrict__ C) {
    extern __shared__ __align__(1024) unsigned char sm[];
    __shared__ __align__(8) uint64_t mb_full[NST];
    const int tid = threadIdx.x;
    const int lane = tid & 31, warp = tid >> 5;
    const int wm = warp >> 2, wn = warp & 3;
    const int lr = lane & 15, lh = lane >> 4;
    const int rowBase = blockIdx.y * 128, colBase = blockIdx.x * 128;
    const char* pA0 = (const char*)Ahi + (long)(rowBase >> 7) * 4 * 8192;
    const char* pA1 = (const char*)Alo + (long)(rowBase >> 7) * 4 * 8192;
    const char* pB  = (const char*)B + (long)(colBase >> 7) * 4 * 8192;
    float acc[4][4][4];
    gemm_core<4, 4, 1>(smem_u32(sm), mb_full, pA0, pA1, pB, tid, lr, lh, wm, wn, acc);
    #pragma unroll
    for (int mi = 0; mi < 4; mi++) {
        int r0 = rowBase + wm*64 + mi*16 + (lane >> 2);
        #pragma unroll
        for (int ni = 0; ni < 4; ni++) {
            int c0 = colBase + wn*32 + ni*8 + (lane & 3)*2;
            float p0 = p1[c0], pp1 = p1[c0+1];
            float2 v0, v1;
            v0.x = -expf(p0  + acc[mi][ni][0]); v0.y = -expf(pp1 + acc[mi][ni][1]);
            v1.x = -expf(p0  + acc[mi][ni][2]); v1.y = -expf(pp1 + acc[mi][ni][3]);
            *(float2*)&C[(long)r0*AA + c0]     = v0;
            *(float2*)&C[(long)(r0+8)*AA + c0] = v1;
        }
    }
}

// ---------------- recurrence: split-K, 128 threads per (b,h) ----------------
__global__ void scan_kernel(const float* __restrict__ kv_state,
                            const float* __restrict__ faaaa) {
    int b = blockIdx.x / HH, h = blockIdx.x % HH;
    int tid = threadIdx.x;
    int half = tid >> 6;
    int v = tid & 63;
    __shared__ float r_sh[2][ZZ], k_sh[2][ZZ], ew_sh[2][ZZ], o_sh[2][ZZ];
    __shared__ float part[2][2];

    float S[32];
    const float* Sin = kv_state + ((long)(b*HH + h) * ZZ) * ZZ;
    #pragma unroll
    for (int j=0;j<32;j++) S[j] = Sin[(half*32+j)*ZZ + v];

    float uv = faaaa[h*ZZ + v];
    long base = (long)(b*TT) * AA + h*ZZ;
    float reset_b = g_reset[b];
    int lane = tid & 31, wrp = tid >> 5;

    float rv = 0.f, kvv = 0.f, wl = 0.f;
    float vv = g_v[base + v];
    if (half == 0) {
        rv  = g_r[base + v];
        kvv = g_k[base + v];
        wl  = g_w[base + v] + reset_b;
    }

    for (int t=0;t<TT;t++) {
        int bi = t & 1;
        if (half == 0) {
            r_sh[bi][v]  = rv;
            k_sh[bi][v]  = kvv;
            ew_sh[bi][v] = expf(wl);
            float p = rv * uv * kvv;
            #pragma unroll
            for (int off=16; off; off >>= 1) p += __shfl_xor_sync(0xffffffffu, p, off);
            if (lane == 0) part[bi][wrp] = p;
        }
        __syncthreads();

        float rv_n = 0.f, kv_n = 0.f, wl_n = 0.f, vv_n = 0.f;
        if (t + 1 < TT) {
            long nb = base + (long)(t+1)*AA;
            vv_n = g_v[nb + v];
            if (half == 0) {
                rv_n = g_r[nb + v];
                kv_n = g_k[nb + v];
                wl_n = g_w[nb + v];
            }
        }

        float ruk = part[bi][0] + part[bi][1];
        const float* rs  = r_sh[bi]  + half*32;
        const float* ks  = k_sh[bi]  + half*32;
        const float* ews = ew_sh[bi] + half*32;
        float o0 = 0.f, o1 = 0.f, o2 = 0.f, o3 = 0.f;
        #pragma unroll
        for (int j=0;j<32;j+=4) {
            o0 = fmaf(rs[j],   S[j],   o0); S[j]   = fmaf(ews[j],   S[j],   ks[j]*vv);
            o1 = fmaf(rs[j+1], S[j+1], o1); S[j+1] = fmaf(ews[j+1], S[j+1], ks[j+1]*vv);
            o2 = fmaf(rs[j+2], S[j+2], o2); S[j+2] = fmaf(ews[j+2], S[j+2], ks[j+2]*vv);
            o3 = fmaf(rs[j+3], S[j+3], o3); S[j+3] = fmaf(ews[j+3], S[j+3], ks[j+3]*vv);
        }
        float o = (o0 + o1) + (o2 + o3);
        if (half == 1) o_sh[bi][v] = o;
        __syncthreads();
        if (half == 0)
            g_xo[base + (long)t*AA + v] = o + o_sh[bi][v] + ruk * vv;

        rv = rv_n; kvv = kv_n; wl = wl_n; vv = vv_n;
    }
}

// ---------------- groupnorm + gate -> tiled A-layout (fp16 split) ----------------
__global__ void gn_gate_kernel(const float* __restrict__ ln_w,
                               const float* __restrict__ ln_b) {
    int gid = blockIdx.x * (blockDim.x >> 5) + (threadIdx.x >> 5);
    int lane = threadIdx.x & 31;
    if (gid >= MR*HH) return;
    int bt = gid / HH, h = gid % HH;
    long base = (long)bt*CC + h*ZZ;
    float x0 = g_xo[base + lane];
    float x1 = g_xo[base + lane + 32];
    float s = x0 + x1;
    #pragma unroll
    for (int off=16; off; off >>= 1) s += __shfl_xor_sync(0xffffffffu, s, off);
    float mu = s * (1.0f/64.0f);
    float d0 = x0 - mu, d1 = x1 - mu;
    float q = d0*d0 + d1*d1;
    #pragma unroll
    for (int off=16; off; off >>= 1) q += __shfl_xor_sync(0xffffffffu, q, off);
    float rs = rsqrtf(q * (1.0f/64.0f) + EPS_GN);
    int c0 = h*ZZ + lane, c1 = c0 + 32;
    float g0 = (d0 * rs * ln_w[c0] + ln_b[c0]) * g_gate[base + lane];
    float g1 = (d1 * rs * ln_w[c1] + ln_b[c1]) * g_gate[base + lane + 32];
    long b0 = a_tile_byte(bt, c0 & ~7) + (c0 & 7)*2;
    long b1 = a_tile_byte(bt, c1 & ~7) + (c1 & 7)*2;
    __half h0 = __float2half_rn(g0);
    __half h1 = __float2half_rn(g1);
    *(__half*)((char*)g_g_hi + b0) = h0;
    *(__half*)((char*)g_g_lo + b0) = __float2half_rn(g0 - __half2float(h0));
    *(__half*)((char*)g_g_hi + b1) = h1;
    *(__half*)((char*)g_g_lo + b1) = __float2half_rn(g1 - __half2float(h1));
}

// ---------------- launch ----------------
extern "C" void kernel_launch(void* const* d_in, const int* in_sizes, int n_in,
                              void* d_out, int out_size) {
    const float* x        = (const float*)d_in[0];
    const int*   pos      = (const int*)  d_in[1];
    const float* kv_state = (const float*)d_in[2];
    const float* shift_st = (const float*)d_in[3];
    const float* maa_x    = (const float*)d_in[4];
    const float* maa_f[5] = { (const float*)d_in[5], (const float*)d_in[6],
                              (const float*)d_in[7], (const float*)d_in[8],
                              (const float*)d_in[9] };       // w,k,v,r,g
    const float* w1       = (const float*)d_in[10];
    const float* w2       = (const float*)d_in[11];
    const float* tdecay   = (const float*)d_in[12];
    const float* tdw1     = (const float*)d_in[13];
    const float* tdw2     = (const float*)d_in[14];
    const float* faaaa    = (const float*)d_in[15];
    const float* Wmat[5]  = { (const float*)d_in[16], (const float*)d_in[17],
                              (const float*)d_in[18], (const float*)d_in[19],
                              (const float*)d_in[20] };      // W_r,W_k,W_v,W_g,W_o
    const float* ln_w     = (const float*)d_in[21];
    const float* ln_b     = (const float*)d_in[22];
    float* out = (float*)d_out;

    float *rb, *kb, *vb, *gateb, *wb;
    __half *xxh, *xxl, *w1h, *tdh, *Wh, *ah, *al, *gh, *gl;
    __half *mth, *mtl, *tdsh, *tdsl, *w2h, *tdw2h;
    cudaGetSymbolAddress((void**)&rb,   g_r);
    cudaGetSymbolAddress((void**)&kb,   g_k);
    cudaGetSymbolAddress((void**)&vb,   g_v);
    cudaGetSymbolAddress((void**)&gateb,g_gate);
    cudaGetSymbolAddress((void**)&wb,   g_w);
    cudaGetSymbolAddress((void**)&xxh,  g_xxx_hi);
    cudaGetSymbolAddress((void**)&xxl,  g_xxx_lo);
    cudaGetSymbolAddress((void**)&w1h,  g_w1_h);
    cudaGetSymbolAddress((void**)&tdh,  g_tdw1_h);
    cudaGetSymbolAddress((void**)&Wh,   g_W_h);
    cudaGetSymbolAddress((void**)&ah,   g_act_hi);
    cudaGetSymbolAddress((void**)&al,   g_act_lo);
    cudaGetSymbolAddress((void**)&gh,   g_g_hi);
    cudaGetSymbolAddress((void**)&gl,   g_g_lo);
    cudaGetSymbolAddress((void**)&mth,  g_mixt_hi);
    cudaGetSymbolAddress((void**)&mtl,  g_mixt_lo);
    cudaGetSymbolAddress((void**)&tdsh, g_td_hi);
    cudaGetSymbolAddress((void**)&tdsl, g_td_lo);
    cudaGetSymbolAddress((void**)&w2h,  g_w2_h);
    cudaGetSymbolAddress((void**)&tdw2h,g_tdw2_h);

    const int SM128  = 3 * (2*8192 + 8192);     // split MI=4: 73728
    const int SM128S = 3 * (8192 + 8192);       // single MI=4: 49152
    const int SM64   = 3 * (2*4096 + 8192);     // split MI=2: 49152
    const int SMMIX  = (2*8192 + 8192);         // 24576
    cudaFuncSetAttribute((const void*)hgemm2p<0,1>,         cudaFuncAttributeMaxDynamicSharedMemorySize, SM128);
    cudaFuncSetAttribute((const void*)hgemm2p<2,0>,         cudaFuncAttributeMaxDynamicSharedMemorySize, SM128S);
    cudaFuncSetAttribute((const void*)hgemm_tanh_split<2,8>,cudaFuncAttributeMaxDynamicSharedMemorySize, SM64);
    cudaFuncSetAttribute((const void*)hgemm_tanh_split<2,4>,cudaFuncAttributeMaxDynamicSharedMemorySize, SM64);
    cudaFuncSetAttribute((const void*)hgemm_mix,            cudaFuncAttributeMaxDynamicSharedMemorySize, SMMIX);
    cudaFuncSetAttribute((const void*)hgemm_decay,          cudaFuncAttributeMaxDynamicSharedMemorySize, SM128);

    const long WC = (long)CC * AA;
    MixP mp; for (int i=0;i<5;i++) mp.maa[i] = maa_f[i];
    W5 w5; for (int i=0;i<5;i++) w5.p[i] = Wmat[i];

    // ---- fork: weight packs on side stream ----
    cudaStream_t s2;
    cudaStreamCreate(&s2);
    cudaEvent_t eFork, eJoin, eAct, eGate;
    cudaEventCreate(&eFork);
    cudaEventCreate(&eJoin);
    cudaEventCreate(&eAct);
    cudaEventCreate(&eGate);
    cudaEventRecord(eFork, 0);
    cudaStreamWaitEvent(s2, eFork, 0);
    pack5_kernel<<<(5*KDIM*(AA/8) + 255)/256, 256, 0, s2>>>(w5, Wh);
    padsplit_kernel<<<(KDIM*(NTD/8) + 255)/256, 256, 0, s2>>>(tdw1, tdh, TDX, NTD);
    pack_tdw2_kernel<<<(NTD*(AA/8) + 255)/256, 256, 0, s2>>>(tdw2, tdw2h);
    cudaEventRecord(eJoin, s2);

    // main: activation chain
    mixx_kernel<<<(MR*CC/8 + 255)/256, 256>>>(x, maa_x, pos, shift_st);
    padsplit_kernel<<<(KDIM*(NMIX/8) + 255)/256, 256>>>(w1, w1h, 5*TMX, NMIX);
    hgemm_tanh_split<2,8><<<dim3(NMIX/128, MR/64), 256, SM64>>>(xxh, xxl, w1h, mth, mtl);
    pack_w2_kernel<<<(5*TMX*(CC/8) + 255)/256, 256>>>(w2, w2h);
    hgemm_mix<<<dim3(CC/128, MR/128, 5), 256, SMMIX>>>(mth, mtl, w2h, mp, x, ah, al);
    cudaEventRecord(eAct, 0);
    cudaStreamWaitEvent(0, eJoin, 0);

    // side stream: gate projection (single-pass A) overlapping td/decay/scan
    cudaStreamWaitEvent(s2, eAct, 0);
    hgemm2p<2,0><<<PGRID, 256, SM128S, s2>>>(ah + 4L*MR*CC, al, Wh + 3*WC, gateb, AA, 3);
    cudaEventRecord(eGate, s2);

    // main: r, k, v projections (split)
    hgemm2p<0,1><<<PGRID, 256, SM128>>>(ah + 3L*MR*CC, al + 3L*MR*CC, Wh + 0*WC, rb, AA, 0);
    hgemm2p<0,1><<<PGRID, 256, SM128>>>(ah + 1L*MR*CC, al + 1L*MR*CC, Wh + 1*WC, kb, AA, 1);
    hgemm2p<0,1><<<PGRID, 256, SM128>>>(ah + 2L*MR*CC, al + 2L*MR*CC, Wh + 2*WC, vb, AA, 2);
    // td + decay + scan
    hgemm_tanh_split<2,4><<<dim3(NTD/128, MR/64), 256, SM64>>>(ah, al, tdh, tdsh, tdsl);
    hgemm_decay<<<dim3(AA/128, MR/128), 256, SM128>>>(tdsh, tdsl, tdw2h, tdecay, wb);
    scan_kernel<<<BB*HH, 128>>>(kv_state, faaaa);
    // join gate, then groupnorm + out projection
    cudaStreamWaitEvent(0, eGate, 0);
    gn_gate_kernel<<<(MR*HH + 7)/8, 256>>>(ln_w, ln_b);
    hgemm2p<0,1><<<PGRID, 256, SM128>>>(gh, gl, Wh + 4*WC, out, CC, 4);
}

// round 17
// speedup vs baseline: 1.1563x; 1.0537x over previous
#include <cuda_runtime.h>
#include <cuda_fp16.h>
#include <math.h>
#include <stdint.h>

// ---------------- problem dims ----------------
#define BB   8
#define TT   512
#define CC   2048
#define HH   32
#define ZZ   64
#define AA   2048
#define MR   (BB*TT)         // 4096
#define TMX  32
#define TDX  64
#define NMIX 256
#define NTD  128
#define EPS_GN (1e-5f * 64.0f)

#define KDIM    2048
#define KCHUNKS 64
#define NST     3
#define PGRID   296

// ---------------- scratch ----------------
__device__ float g_shift[BB*CC];
__device__ float g_reset[BB];
__device__ int   g_ctr[8];
__device__ __align__(1024) __half g_xxx_hi[MR*CC];
__device__ __align__(1024) __half g_xxx_lo[MR*CC];
__device__ __align__(1024) __half g_act_hi[5u*MR*CC];
__device__ __align__(1024) __half g_act_lo[5u*MR*CC];
__device__ __align__(1024) __half g_g_hi[MR*AA];
__device__ __align__(1024) __half g_g_lo[MR*AA];
__device__ __align__(1024) __half g_mixt_hi[MR*NMIX];
__device__ __align__(1024) __half g_mixt_lo[MR*NMIX];
__device__ __align__(1024) __half g_td_hi[MR*NTD];
__device__ __align__(1024) __half g_td_lo[MR*NTD];
__device__ __align__(1024) __half g_w1_h[CC*NMIX];
__device__ __align__(1024) __half g_tdw1_h[CC*NTD];
__device__ __align__(1024) __half g_W_h[5u*CC*AA];
__device__ __align__(1024) __half g_w2_h[5u*TMX*CC];
__device__ __align__(1024) __half g_tdw2_h[NTD*AA];
__device__ float g_r[MR*AA];
__device__ float g_k[MR*AA];
__device__ float g_v[MR*AA];
__device__ float g_gate[MR*AA];
__device__ float g_w[MR*AA];
__device__ float g_xo[MR*AA];

// ---------------- helpers ----------------
__device__ __forceinline__ uint32_t smem_u32(const void* p) {
    return (uint32_t)__cvta_generic_to_shared(p);
}
template<int EPI>
__device__ __forceinline__ float hepi(float a) {
    if (EPI == 2) return a / (1.0f + expf(-a));
    return a;
}
__device__ __forceinline__ void mbar_wait(uint32_t mb, uint32_t parity) {
    asm volatile(
        "{\n\t.reg .pred P;\n\t"
        "WL%=:\n\t"
        "mbarrier.try_wait.parity.shared.b64 P, [%0], %1;\n\t"
        "@P bra WD%=;\n\t"
        "bra WL%=;\n\t"
        "WD%=:\n\t}"
        :: "r"(mb), "r"(parity) : "memory");
}
__device__ __forceinline__ long a_tile_byte_k(int m, int k0, int nc) {
    int r = m & 127, g = (k0 & 31) >> 3;
    return ((long)((m >> 7) * nc + (k0 >> 5))) * 8192 + r*64 + ((g ^ ((r>>1)&3)) << 4);
}
__device__ __forceinline__ long b_tile_byte_k(int k, int n0, int nc) {
    int kr = k & 31, gn = (n0 & 127) >> 3;
    return ((long)((n0 >> 7) * nc + (k >> 5))) * 8192 + kr*256 + ((gn ^ (kr&7)) << 4);
}
__device__ __forceinline__ long a_tile_byte(int m, int k0) { return a_tile_byte_k(m, k0, KCHUNKS); }
__device__ __forceinline__ long b_tile_byte(int k, int n0) { return b_tile_byte_k(k, n0, KCHUNKS); }

__device__ __forceinline__ void split8_store_h(const float* v, char* hi, char* lo, long byte) {
    uint32_t ph[4], pl[4];
    #pragma unroll
    for (int j = 0; j < 4; j++) {
        __half h0 = __float2half_rn(v[2*j]);
        __half h1 = __float2half_rn(v[2*j+1]);
        float l0 = v[2*j]   - __half2float(h0);
        float l1 = v[2*j+1] - __half2float(h1);
        __half2 hh; hh.x = h0; hh.y = h1;
        __half2 ll; ll.x = __float2half_rn(l0); ll.y = __float2half_rn(l1);
        ph[j] = *(uint32_t*)&hh; pl[j] = *(uint32_t*)&ll;
    }
    *(uint4*)(hi + byte) = make_uint4(ph[0], ph[1], ph[2], ph[3]);
    *(uint4*)(lo + byte) = make_uint4(pl[0], pl[1], pl[2], pl[3]);
}
__device__ __forceinline__ void pack8_store_h(const float* v, char* dst, long byte) {
    uint32_t p[4];
    #pragma unroll
    for (int j = 0; j < 4; j++) {
        __half2 hh; hh.x = __float2half_rn(v[2*j]); hh.y = __float2half_rn(v[2*j+1]);
        p[j] = *(uint32_t*)&hh;
    }
    *(uint4*)(dst + byte) = make_uint4(p[0], p[1], p[2], p[3]);
}
__device__ __forceinline__ void split2_store_h(float v0, float v1, char* hi, char* lo, long byte) {
    __half h0 = __float2half_rn(v0), h1 = __float2half_rn(v1);
    __half2 hh; hh.x = h0; hh.y = h1;
    __half2 ll; ll.x = __float2half_rn(v0 - __half2float(h0));
    ll.y = __float2half_rn(v1 - __half2float(h1));
    *(__half2*)(hi + byte) = hh;
    *(__half2*)(lo + byte) = ll;
}

// ---------------- fused prep + xxx (also resets tile counters) ----------------
__global__ void mixx_kernel(const float* __restrict__ x,
                            const float* __restrict__ maa_x,
                            const int* __restrict__ positions,
                            const float* __restrict__ shift_state) {
    int idx = blockIdx.x * blockDim.x + threadIdx.x;
    if (idx < 8) g_ctr[idx] = 0;
    if (idx >= MR*CC/8) return;
    int m  = idx >> 8;
    int k0 = (idx & 255) << 3;
    int b  = m / TT;
    float rst = (positions[b*TT] == 0) ? -100.0f : 0.0f;
    float erst = expf(rst);
    float v[8];
    #pragma unroll
    for (int e = 0; e < 8; e++) {
        int c = k0 + e;
        float sh = shift_state[b*CC + c] * erst;
        if ((m % TT) == 0) g_shift[b*CC + c] = sh;
        float xv = x[(long)m*CC + c];
        v[e] = xv + (sh - xv) * maa_x[c];
    }
    if ((m % TT) == 0 && k0 == 0) g_reset[b] = rst;
    split8_store_h(v, (char*)g_xxx_hi, (char*)g_xxx_lo, a_tile_byte(m, k0));
}

// ---------------- pad fp32 [K=2048,Nsrc] -> fp16 tiled B-layout ----------------
__global__ void padsplit_kernel(const float* __restrict__ src,
                                __half* __restrict__ dst,
                                int Nsrc, int Ndst) {
    int idx = blockIdx.x * blockDim.x + threadIdx.x;
    int gpr = Ndst >> 3;
    if (idx >= KDIM*gpr) return;
    int k  = idx / gpr;
    int n0 = (idx % gpr) << 3;
    float v[8];
    #pragma unroll
    for (int e = 0; e < 8; e++) {
        int n = n0 + e;
        v[e] = (n < Nsrc) ? src[(long)k*Nsrc + n] : 0.0f;
    }
    pack8_store_h(v, (char*)dst, b_tile_byte(k, n0));
}

// ---------------- fused pack of all five [2048,2048] weights ----------------
struct W5 { const float* p[5]; };
__global__ void pack5_kernel(W5 w, __half* __restrict__ dst) {
    int idx = blockIdx.x * blockDim.x + threadIdx.x;
    const int per_f = KDIM * (AA/8);
    if (idx >= 5*per_f) return;
    int f = idx / per_f, rem = idx % per_f;
    int k = rem / (AA/8);
    int n0 = (rem % (AA/8)) << 3;
    const float* src = w.p[f];
    float v[8];
    #pragma unroll
    for (int e = 0; e < 8; e++) v[e] = src[(long)k*AA + n0 + e];
    pack8_store_h(v, (char*)dst + (long)f*CC*AA*2, b_tile_byte(k, n0));
}

// ---------------- pack w2 [5,32,CC] -> 5 x B-layout (kc=1) ----------------
__global__ void pack_w2_kernel(const float* __restrict__ w2, __half* __restrict__ dst) {
    int idx = blockIdx.x * blockDim.x + threadIdx.x;
    const int per_f = TMX * (CC/8);
    if (idx >= 5*per_f) return;
    int f = idx / per_f, rem = idx % per_f;
    int k = rem / (CC/8);
    int n0 = (rem % (CC/8)) << 3;
    float v[8];
    #pragma unroll
    for (int e = 0; e < 8; e++) v[e] = w2[(long)f*TMX*CC + (long)k*CC + n0 + e];
    pack8_store_h(v, (char*)dst + (long)f*TMX*CC*2, b_tile_byte_k(k, n0, 1));
}

// ---------------- pack tdw2 [64,AA] -> B-layout K padded to 128 (kc=4) ----------------
__global__ void pack_tdw2_kernel(const float* __restrict__ tdw2, __half* __restrict__ dst) {
    int idx = blockIdx.x * blockDim.x + threadIdx.x;
    if (idx >= NTD*(AA/8)) return;
    int k = idx / (AA/8);
    int n0 = (idx % (AA/8)) << 3;
    float v[8];
    #pragma unroll
    for (int e = 0; e < 8; e++) v[e] = (k < TDX) ? tdw2[(long)k*AA + n0 + e] : 0.0f;
    pack8_store_h(v, (char*)dst, b_tile_byte_k(k, n0, 4));
}

// ---------------- core GEMM: MI*32 x 128 tile, NC K-chunks, SPLIT=1 -> hi+lo A ----------------
template<int MI, int NC, int SPLIT>
__device__ __forceinline__ void gemm_core(
        uint32_t sb, uint64_t* mb_full,
        const char* pA0, const char* pA1, const char* pB,
        int tid, int lr, int lh, int wm, int wn,
        float acc[MI][4][4]) {
    constexpr int ASLOT = MI * 2048;
    constexpr int NAB   = SPLIT ? 2 : 1;
    constexpr int STGB  = NAB*ASLOT + 8192;

    if (tid == 0) {
        #pragma unroll
        for (int s = 0; s < NST; s++)
            asm volatile("mbarrier.init.shared.b64 [%0], 1;"
                         :: "r"(smem_u32(&mb_full[s])) : "memory");
    }
    __syncthreads();

    auto arm = [&](int c) {
        int s = c % NST;
        uint32_t st = sb + s*STGB;
        uint32_t mb = smem_u32(&mb_full[s]);
        long o = (long)c * 8192;
        asm volatile("mbarrier.arrive.expect_tx.shared.b64 _, [%0], %1;"
                     :: "r"(mb), "r"((uint32_t)STGB) : "memory");
        asm volatile("cp.async.bulk.shared::cluster.global.mbarrier::complete_tx::bytes [%0], [%1], %2, [%3];"
                     :: "r"(st), "l"(pA0 + o), "r"((uint32_t)ASLOT), "r"(mb) : "memory");
        if (SPLIT)
            asm volatile("cp.async.bulk.shared::cluster.global.mbarrier::complete_tx::bytes [%0], [%1], %2, [%3];"
                         :: "r"(st + ASLOT), "l"(pA1 + o), "r"((uint32_t)ASLOT), "r"(mb) : "memory");
        asm volatile("cp.async.bulk.shared::cluster.global.mbarrier::complete_tx::bytes [%0], [%1], %2, [%3];"
                     :: "r"(st + NAB*ASLOT), "l"(pB + o), "r"(8192u), "r"(mb) : "memory");
    };
    constexpr int PRIME = (NC < NST) ? NC : NST;
    if (tid == 0) {
        #pragma unroll
        for (int c = 0; c < PRIME; c++) arm(c);
    }

    #pragma unroll
    for (int a=0;a<MI;a++)
        #pragma unroll
        for (int b2=0;b2<4;b2++)
            #pragma unroll
            for (int d=0;d<4;d++) acc[a][b2][d]=0.f;

    #pragma unroll 1
    for (int c = 0; c < NC; c++) {
        int s = c % NST;
        uint32_t par = (uint32_t)((c / NST) & 1);
        mbar_wait(smem_u32(&mb_full[s]), par);

        uint32_t st = sb + s*STGB;
        #pragma unroll
        for (int ks = 0; ks < 2; ks++) {
            uint32_t ah[MI][4], al[MI][4], bh[4][2];
            #pragma unroll
            for (int mi = 0; mi < MI; mi++) {
                int row = wm*(MI*16) + mi*16 + lr;
                int g = ks*2 + lh;
                uint32_t off = row*64 + ((g ^ ((row>>1)&3)) << 4);
                asm volatile("ldmatrix.sync.aligned.m8n8.x4.shared.b16 {%0,%1,%2,%3}, [%4];"
                    : "=r"(ah[mi][0]),"=r"(ah[mi][1]),"=r"(ah[mi][2]),"=r"(ah[mi][3])
                    : "r"(st + off));
                if (SPLIT)
                    asm volatile("ldmatrix.sync.aligned.m8n8.x4.shared.b16 {%0,%1,%2,%3}, [%4];"
                        : "=r"(al[mi][0]),"=r"(al[mi][1]),"=r"(al[mi][2]),"=r"(al[mi][3])
                        : "r"(st + ASLOT + off));
            }
            #pragma unroll
            for (int ni = 0; ni < 4; ni++) {
                int kr = ks*16 + lr;
                int gn = wn*4 + ni;
                uint32_t off = kr*256 + ((gn ^ (kr & 7)) << 4);
                asm volatile("ldmatrix.sync.aligned.m8n8.x2.trans.shared.b16 {%0,%1}, [%2];"
                    : "=r"(bh[ni][0]),"=r"(bh[ni][1]) : "r"(st + NAB*ASLOT + off));
            }
            #pragma unroll
            for (int mi = 0; mi < MI; mi++)
                #pragma unroll
                for (int ni = 0; ni < 4; ni++)
                    asm volatile("mma.sync.aligned.m16n8k16.row.col.f32.f16.f16.f32 "
                        "{%0,%1,%2,%3}, {%4,%5,%6,%7}, {%8,%9}, {%0,%1,%2,%3};"
                        : "+f"(acc[mi][ni][0]),"+f"(acc[mi][ni][1]),
                          "+f"(acc[mi][ni][2]),"+f"(acc[mi][ni][3])
                        : "r"(ah[mi][0]),"r"(ah[mi][1]),"r"(ah[mi][2]),"r"(ah[mi][3]),
                          "r"(bh[ni][0]),"r"(bh[ni][1]));
            if (SPLIT) {
                #pragma unroll
                for (int mi = 0; mi < MI; mi++)
                    #pragma unroll
                    for (int ni = 0; ni < 4; ni++)
                        asm volatile("mma.sync.aligned.m16n8k16.row.col.f32.f16.f16.f32 "
                            "{%0,%1,%2,%3}, {%4,%5,%6,%7}, {%8,%9}, {%0,%1,%2,%3};"
                            : "+f"(acc[mi][ni][0]),"+f"(acc[mi][ni][1]),
                              "+f"(acc[mi][ni][2]),"+f"(acc[mi][ni][3])
                            : "r"(al[mi][0]),"r"(al[mi][1]),"r"(al[mi][2]),"r"(al[mi][3]),
                              "r"(bh[ni][0]),"r"(bh[ni][1]));
            }
        }
        __syncthreads();
        if (tid == 0 && c + NST < NC) arm(c + NST);
    }
}

// ---------------- persistent big GEMM ----------------
template<int EPI, int SPLIT>
__global__ void __launch_bounds__(256, 2)
hgemm2p(const __half* __restrict__ Ahi, const __half* __restrict__ Alo,
        const __half* __restrict__ B, float* __restrict__ C, int N, int ctrIdx) {
    extern __shared__ __align__(1024) unsigned char sm[];
    __shared__ __align__(8) uint64_t mb_full[NST];
    __shared__ int s_tile;
    const int tid = threadIdx.x;
    const int lane = tid & 31, warp = tid >> 5;
    const int wm = warp >> 2, wn = warp & 3;
    const int lr = lane & 15, lh = lane >> 4;
    const int numTiles = (MR/128) * (N/128);
    const int rowTiles = MR/128;

    if (tid == 0) s_tile = atomicAdd(&g_ctr[ctrIdx], 1);
    __syncthreads();
    int tile = s_tile;

    while (tile < numTiles) {
        int by = tile % rowTiles;
        int bx = tile / rowTiles;
        int rowBase = by * 128, colBase = bx * 128;
        const char* pA0 = (const char*)Ahi + (long)(rowBase >> 7) * KCHUNKS * 8192;
        const char* pA1 = (const char*)Alo + (long)(rowBase >> 7) * KCHUNKS * 8192;
        const char* pB  = (const char*)B   + (long)(colBase >> 7) * KCHUNKS * 8192;
        float acc[4][4][4];
        gemm_core<4, KCHUNKS, SPLIT>(smem_u32(sm), mb_full, pA0, pA1, pB, tid, lr, lh, wm, wn, acc);
        #pragma unroll
        for (int mi = 0; mi < 4; mi++) {
            int r0 = rowBase + wm*64 + mi*16 + (lane >> 2);
            #pragma unroll
            for (int ni = 0; ni < 4; ni++) {
                int c0 = colBase + wn*32 + ni*8 + (lane & 3)*2;
                float2 v0, v1;
                v0.x = hepi<EPI>(acc[mi][ni][0]); v0.y = hepi<EPI>(acc[mi][ni][1]);
                v1.x = hepi<EPI>(acc[mi][ni][2]); v1.y = hepi<EPI>(acc[mi][ni][3]);
                *(float2*)&C[(long)r0*N + c0]     = v0;
                *(float2*)&C[(long)(r0+8)*N + c0] = v1;
            }
        }
        __syncthreads();
        if (tid == 0) s_tile = atomicAdd(&g_ctr[ctrIdx], 1);
        __syncthreads();
        tile = s_tile;
    }
}

// ---------------- tanh GEMM -> split-fp16 A-layout (mixt NCOUT=8, td NCOUT=4) ----------------
template<int MI, int NCOUT>
__global__ void __launch_bounds__(256, 2)
hgemm_tanh_split(const __half* __restrict__ Ahi, const __half* __restrict__ Alo,
                 const __half* __restrict__ B,
                 __half* __restrict__ Ohi, __half* __restrict__ Olo) {
    extern __shared__ __align__(1024) unsigned char sm[];
    __shared__ __align__(8) uint64_t mb_full[NST];
    const int tid = threadIdx.x;
    const int lane = tid & 31, warp = tid >> 5;
    const int wm = warp >> 2, wn = warp & 3;
    const int lr = lane & 15, lh = lane >> 4;
    const int rowBase = blockIdx.y * (MI*32), colBase = blockIdx.x * 128;
    const long aoff = (long)(rowBase >> 7) * KCHUNKS * 8192 + (long)((rowBase >> 5) & 3) * 2048;
    const char* pA0 = (const char*)Ahi + aoff;
    const char* pA1 = (const char*)Alo + aoff;
    const char* pB  = (const char*)B + (long)(colBase >> 7) * KCHUNKS * 8192;
    float acc[MI][4][4];
    gemm_core<MI, KCHUNKS, 1>(smem_u32(sm), mb_full, pA0, pA1, pB, tid, lr, lh, wm, wn, acc);
    #pragma unroll
    for (int mi = 0; mi < MI; mi++) {
        int r0 = rowBase + wm*(MI*16) + mi*16 + (lane >> 2);
        #pragma unroll
        for (int ni = 0; ni < 4; ni++) {
            int c0 = colBase + wn*32 + ni*8 + (lane & 3)*2;
            int e2 = (c0 & 7) * 2;
            long ba = a_tile_byte_k(r0,   c0 & ~7, NCOUT) + e2;
            long bb = a_tile_byte_k(r0+8, c0 & ~7, NCOUT) + e2;
            split2_store_h(tanhf(acc[mi][ni][0]), tanhf(acc[mi][ni][1]), (char*)Ohi, (char*)Olo, ba);
            split2_store_h(tanhf(acc[mi][ni][2]), tanhf(acc[mi][ni][3]), (char*)Ohi, (char*)Olo, bb);
        }
    }
}

// ---------------- mix GEMM (K=32, per-f) -> act_f split-fp16 A-layout ----------------
struct MixP { const float* maa[5]; };
__global__ void __launch_bounds__(256, 2)
hgemm_mix(const __half* __restrict__ Mhi, const __half* __restrict__ Mlo,
          const __half* __restrict__ W2, MixP mp,
          const float* __restrict__ x,
          __half* __restrict__ Ohi, __half* __restrict__ Olo) {
    extern __shared__ __align__(1024) unsigned char sm[];
    __shared__ __align__(8) uint64_t mb_full[NST];
    const int tid = threadIdx.x;
    const int lane = tid & 31, warp = tid >> 5;
    const int wm = warp >> 2, wn = warp & 3;
    const int lr = lane & 15, lh = lane >> 4;
    const int f = blockIdx.z;
    const int rowBase = blockIdx.y * 128, colBase = blockIdx.x * 128;
    const char* pA0 = (const char*)Mhi + ((long)(rowBase >> 7) * 8 + f) * 8192;
    const char* pA1 = (const char*)Mlo + ((long)(rowBase >> 7) * 8 + f) * 8192;
    const char* pB  = (const char*)W2 + (long)f*TMX*CC*2 + (long)(colBase >> 7) * 8192;
    float acc[4][4][4];
    gemm_core<4, 1, 1>(smem_u32(sm), mb_full, pA0, pA1, pB, tid, lr, lh, wm, wn, acc);

    const float* maa = mp.maa[f];
    char* oh = (char*)Ohi + (long)f*MR*CC*2;
    char* ol = (char*)Olo + (long)f*MR*CC*2;
    #pragma unroll
    for (int mi = 0; mi < 4; mi++) {
        int r0 = rowBase + wm*64 + mi*16 + (lane >> 2);
        int b0 = r0 / TT, b1 = (r0+8) / TT;
        #pragma unroll
        for (int ni = 0; ni < 4; ni++) {
            int c0 = colBase + wn*32 + ni*8 + (lane & 3)*2;
            float ma0 = maa[c0], ma1 = maa[c0+1];
            int e2 = (c0 & 7) * 2;
            {
                float xv0 = x[(long)r0*CC + c0], xv1 = x[(long)r0*CC + c0 + 1];
                float s0 = g_shift[b0*CC + c0], s1 = g_shift[b0*CC + c0 + 1];
                float v0 = xv0 + (s0 - xv0) * (ma0 + acc[mi][ni][0]);
                float v1 = xv1 + (s1 - xv1) * (ma1 + acc[mi][ni][1]);
                split2_store_h(v0, v1, oh, ol, a_tile_byte_k(r0, c0 & ~7, KCHUNKS) + e2);
            }
            {
                float xv0 = x[(long)(r0+8)*CC + c0], xv1 = x[(long)(r0+8)*CC + c0 + 1];
                float s0 = g_shift[b1*CC + c0], s1 = g_shift[b1*CC + c0 + 1];
                float v0 = xv0 + (s0 - xv0) * (ma0 + acc[mi][ni][2]);
                float v1 = xv1 + (s1 - xv1) * (ma1 + acc[mi][ni][3]);
                split2_store_h(v0, v1, oh, ol, a_tile_byte_k(r0+8, c0 & ~7, KCHUNKS) + e2);
            }
        }
    }
}

// ---------------- decay GEMM (K=128, NC=4): w = -exp(tdecay + td @ tdw2) ----------------
__global__ void __launch_bounds__(256, 2)
hgemm_decay(const __half* __restrict__ Ahi, const __half* __restrict__ Alo,
            const __half* __restrict__ B, const float* __restrict__ p1,
            float* __restrict__ C) {
    extern __shared__ __align__(1024) unsigned char sm[];
    __shared__ __align__(8) uint64_t mb_full[NST];
    const int tid = threadIdx.x;
    const int lane = tid & 31, warp = tid >> 5;
    const int wm = warp >> 2, wn = warp & 3;
    const int lr = lane & 15, lh = lane >> 4;
    const int rowBase = blockIdx.y * 128, colBase = blockIdx.x * 128;
    const char* pA0 = (const char*)Ahi + (long)(rowBase >> 7) * 4 * 8192;
    const char* pA1 = (const char*)Alo + (long)(rowBase >> 7) * 4 * 8192;
    const char* pB  = (const char*)B + (long)(colBase >> 7) * 4 * 8192;
    float acc[4][4][4];
    gemm_core<4, 4, 1>(smem_u32(sm), mb_full, pA0, pA1, pB, tid, lr, lh, wm, wn, acc);
    #pragma unroll
    for (int mi = 0; mi < 4; mi++) {
        int r0 = rowBase + wm*64 + mi*16 + (lane >> 2);
        #pragma unroll
        for (int ni = 0; ni < 4; ni++) {
            int c0 = colBase + wn*32 + ni*8 + (lane & 3)*2;
            float p0 = p1[c0], pp1 = p1[c0+1];
            float2 v0, v1;
            v0.x = -expf(p0  + acc[mi][ni][0]); v0.y = -expf(pp1 + acc[mi][ni][1]);
            v1.x = -expf(p0  + acc[mi][ni][2]); v1.y = -expf(pp1 + acc[mi][ni][3]);
            *(float2*)&C[(long)r0*AA + c0]     = v0;
            *(float2*)&C[(long)(r0+8)*AA + c0] = v1;
        }
    }
}

// ---------------- recurrence: split-K, 128 threads per (b,h) ----------------
__global__ void scan_kernel(const float* __restrict__ kv_state,
                            const float* __restrict__ faaaa) {
    int b = blockIdx.x / HH, h = blockIdx.x % HH;
    int tid = threadIdx.x;
    int half = tid >> 6;
    int v = tid & 63;
    __shared__ float r_sh[2][ZZ], k_sh[2][ZZ], ew_sh[2][ZZ], o_sh[2][ZZ];
    __shared__ float part[2][2];

    float S[32];
    const float* Sin = kv_state + ((long)(b*HH + h) * ZZ) * ZZ;
    #pragma unroll
    for (int j=0;j<32;j++) S[j] = Sin[(half*32+j)*ZZ + v];

    float uv = faaaa[h*ZZ + v];
    long base = (long)(b*TT) * AA + h*ZZ;
    float reset_b = g_reset[b];
    int lane = tid & 31, wrp = tid >> 5;

    float rv = 0.f, kvv = 0.f, wl = 0.f;
    float vv = g_v[base + v];
    if (half == 0) {
        rv  = g_r[base + v];
        kvv = g_k[base + v];
        wl  = g_w[base + v] + reset_b;
    }

    for (int t=0;t<TT;t++) {
        int bi = t & 1;
        if (half == 0) {
            r_sh[bi][v]  = rv;
            k_sh[bi][v]  = kvv;
            ew_sh[bi][v] = expf(wl);
            float p = rv * uv * kvv;
            #pragma unroll
            for (int off=16; off; off >>= 1) p += __shfl_xor_sync(0xffffffffu, p, off);
            if (lane == 0) part[bi][wrp] = p;
        }
        __syncthreads();

        float rv_n = 0.f, kv_n = 0.f, wl_n = 0.f, vv_n = 0.f;
        if (t + 1 < TT) {
            long nb = base + (long)(t+1)*AA;
            vv_n = g_v[nb + v];
            if (half == 0) {
                rv_n = g_r[nb + v];
                kv_n = g_k[nb + v];
                wl_n = g_w[nb + v];
            }
        }

        float ruk = part[bi][0] + part[bi][1];
        const float* rs  = r_sh[bi]  + half*32;
        const float* ks  = k_sh[bi]  + half*32;
        const float* ews = ew_sh[bi] + half*32;
        float o0 = 0.f, o1 = 0.f, o2 = 0.f, o3 = 0.f;
        #pragma unroll
        for (int j=0;j<32;j+=4) {
            o0 = fmaf(rs[j],   S[j],   o0); S[j]   = fmaf(ews[j],   S[j],   ks[j]*vv);
            o1 = fmaf(rs[j+1], S[j+1], o1); S[j+1] = fmaf(ews[j+1], S[j+1], ks[j+1]*vv);
            o2 = fmaf(rs[j+2], S[j+2], o2); S[j+2] = fmaf(ews[j+2], S[j+2], ks[j+2]*vv);
            o3 = fmaf(rs[j+3], S[j+3], o3); S[j+3] = fmaf(ews[j+3], S[j+3], ks[j+3]*vv);
        }
        float o = (o0 + o1) + (o2 + o3);
        if (half == 1) o_sh[bi][v] = o;
        __syncthreads();
        if (half == 0)
            g_xo[base + (long)t*AA + v] = o + o_sh[bi][v] + ruk * vv;

        rv = rv_n; kvv = kv_n; wl = wl_n; vv = vv_n;
    }
}

// ---------------- groupnorm + gate -> tiled A-layout (fp16 split) ----------------
__global__ void gn_gate_kernel(const float* __restrict__ ln_w,
                               const float* __restrict__ ln_b) {
    int gid = blockIdx.x * (blockDim.x >> 5) + (threadIdx.x >> 5);
    int lane = threadIdx.x & 31;
    if (gid >= MR*HH) return;
    int bt = gid / HH, h = gid % HH;
    long base = (long)bt*CC + h*ZZ;
    float x0 = g_xo[base + lane];
    float x1 = g_xo[base + lane + 32];
    float s = x0 + x1;
    #pragma unroll
    for (int off=16; off; off >>= 1) s += __shfl_xor_sync(0xffffffffu, s, off);
    float mu = s * (1.0f/64.0f);
    float d0 = x0 - mu, d1 = x1 - mu;
    float q = d0*d0 + d1*d1;
    #pragma unroll
    for (int off=16; off; off >>= 1) q += __shfl_xor_sync(0xffffffffu, q, off);
    float rs = rsqrtf(q * (1.0f/64.0f) + EPS_GN);
    int c0 = h*ZZ + lane, c1 = c0 + 32;
    float g0 = (d0 * rs * ln_w[c0] + ln_b[c0]) * g_gate[base + lane];
    float g1 = (d1 * rs * ln_w[c1] + ln_b[c1]) * g_gate[base + lane + 32];
    long b0 = a_tile_byte(bt, c0 & ~7) + (c0 & 7)*2;
    long b1 = a_tile_byte(bt, c1 & ~7) + (c1 & 7)*2;
    __half h0 = __float2half_rn(g0);
    __half h1 = __float2half_rn(g1);
    *(__half*)((char*)g_g_hi + b0) = h0;
    *(__half*)((char*)g_g_lo + b0) = __float2half_rn(g0 - __half2float(h0));
    *(__half*)((char*)g_g_hi + b1) = h1;
    *(__half*)((char*)g_g_lo + b1) = __float2half_rn(g1 - __half2float(h1));
}

// ---------------- launch ----------------
extern "C" void kernel_launch(void* const* d_in, const int* in_sizes, int n_in,
                              void* d_out, int out_size) {
    const float* x        = (const float*)d_in[0];
    const int*   pos      = (const int*)  d_in[1];
    const float* kv_state = (const float*)d_in[2];
    const float* shift_st = (const float*)d_in[3];
    const float* maa_x    = (const float*)d_in[4];
    const float* maa_f[5] = { (const float*)d_in[5], (const float*)d_in[6],
                              (const float*)d_in[7], (const float*)d_in[8],
                              (const float*)d_in[9] };       // w,k,v,r,g
    const float* w1       = (const float*)d_in[10];
    const float* w2       = (const float*)d_in[11];
    const float* tdecay   = (const float*)d_in[12];
    const float* tdw1     = (const float*)d_in[13];
    const float* tdw2     = (const float*)d_in[14];
    const float* faaaa    = (const float*)d_in[15];
    const float* Wmat[5]  = { (const float*)d_in[16], (const float*)d_in[17],
                              (const float*)d_in[18], (const float*)d_in[19],
                              (const float*)d_in[20] };      // W_r,W_k,W_v,W_g,W_o
    const float* ln_w     = (const float*)d_in[21];
    const float* ln_b     = (const float*)d_in[22];
    float* out = (float*)d_out;

    float *rb, *kb, *vb, *gateb, *wb;
    __half *xxh, *xxl, *w1h, *tdh, *Wh, *ah, *al, *gh, *gl;
    __half *mth, *mtl, *tdsh, *tdsl, *w2h, *tdw2h;
    cudaGetSymbolAddress((void**)&rb,   g_r);
    cudaGetSymbolAddress((void**)&kb,   g_k);
    cudaGetSymbolAddress((void**)&vb,   g_v);
    cudaGetSymbolAddress((void**)&gateb,g_gate);
    cudaGetSymbolAddress((void**)&wb,   g_w);
    cudaGetSymbolAddress((void**)&xxh,  g_xxx_hi);
    cudaGetSymbolAddress((void**)&xxl,  g_xxx_lo);
    cudaGetSymbolAddress((void**)&w1h,  g_w1_h);
    cudaGetSymbolAddress((void**)&tdh,  g_tdw1_h);
    cudaGetSymbolAddress((void**)&Wh,   g_W_h);
    cudaGetSymbolAddress((void**)&ah,   g_act_hi);
    cudaGetSymbolAddress((void**)&al,   g_act_lo);
    cudaGetSymbolAddress((void**)&gh,   g_g_hi);
    cudaGetSymbolAddress((void**)&gl,   g_g_lo);
    cudaGetSymbolAddress((void**)&mth,  g_mixt_hi);
    cudaGetSymbolAddress((void**)&mtl,  g_mixt_lo);
    cudaGetSymbolAddress((void**)&tdsh, g_td_hi);
    cudaGetSymbolAddress((void**)&tdsl, g_td_lo);
    cudaGetSymbolAddress((void**)&w2h,  g_w2_h);
    cudaGetSymbolAddress((void**)&tdw2h,g_tdw2_h);

    const int SM128  = 3 * (2*8192 + 8192);     // split MI=4: 73728
    const int SM128S = 3 * (8192 + 8192);       // single MI=4: 49152
    const int SM64   = 3 * (2*4096 + 8192);     // split MI=2: 49152
    const int SMMIX  = (2*8192 + 8192);         // 24576
    cudaFuncSetAttribute((const void*)hgemm2p<0,1>,         cudaFuncAttributeMaxDynamicSharedMemorySize, SM128);
    cudaFuncSetAttribute((const void*)hgemm2p<0,0>,         cudaFuncAttributeMaxDynamicSharedMemorySize, SM128S);
    cudaFuncSetAttribute((const void*)hgemm2p<2,0>,         cudaFuncAttributeMaxDynamicSharedMemorySize, SM128S);
    cudaFuncSetAttribute((const void*)hgemm_tanh_split<2,8>,cudaFuncAttributeMaxDynamicSharedMemorySize, SM64);
    cudaFuncSetAttribute((const void*)hgemm_tanh_split<2,4>,cudaFuncAttributeMaxDynamicSharedMemorySize, SM64);
    cudaFuncSetAttribute((const void*)hgemm_mix,            cudaFuncAttributeMaxDynamicSharedMemorySize, SMMIX);
    cudaFuncSetAttribute((const void*)hgemm_decay,          cudaFuncAttributeMaxDynamicSharedMemorySize, SM128);

    const long WC = (long)CC * AA;
    MixP mp; for (int i=0;i<5;i++) mp.maa[i] = maa_f[i];
    W5 w5; for (int i=0;i<5;i++) w5.p[i] = Wmat[i];

    // ---- fork: weight packs on side stream ----
    cudaStream_t s2;
    cudaStreamCreate(&s2);
    cudaEvent_t eFork, eJoin, eAct, eGate;
    cudaEventCreate(&eFork);
    cudaEventCreate(&eJoin);
    cudaEventCreate(&eAct);
    cudaEventCreate(&eGate);
    cudaEventRecord(eFork, 0);
    cudaStreamWaitEvent(s2, eFork, 0);
    pack5_kernel<<<(5*KDIM*(AA/8) + 255)/256, 256, 0, s2>>>(w5, Wh);
    padsplit_kernel<<<(KDIM*(NTD/8) + 255)/256, 256, 0, s2>>>(tdw1, tdh, TDX, NTD);
    pack_tdw2_kernel<<<(NTD*(AA/8) + 255)/256, 256, 0, s2>>>(tdw2, tdw2h);
    cudaEventRecord(eJoin, s2);

    // main: activation chain
    mixx_kernel<<<(MR*CC/8 + 255)/256, 256>>>(x, maa_x, pos, shift_st);
    padsplit_kernel<<<(KDIM*(NMIX/8) + 255)/256, 256>>>(w1, w1h, 5*TMX, NMIX);
    hgemm_tanh_split<2,8><<<dim3(NMIX/128, MR/64), 256, SM64>>>(xxh, xxl, w1h, mth, mtl);
    pack_w2_kernel<<<(5*TMX*(CC/8) + 255)/256, 256>>>(w2, w2h);
    hgemm_mix<<<dim3(CC/128, MR/128, 5), 256, SMMIX>>>(mth, mtl, w2h, mp, x, ah, al);
    cudaEventRecord(eAct, 0);
    cudaStreamWaitEvent(0, eJoin, 0);

    // side stream: gate projection (single-pass A) overlapping td/decay/scan
    cudaStreamWaitEvent(s2, eAct, 0);
    hgemm2p<2,0><<<PGRID, 256, SM128S, s2>>>(ah + 4L*MR*CC, al, Wh + 3*WC, gateb, AA, 3);
    cudaEventRecord(eGate, s2);

    // main: r, k (split) + v (single-pass) projections
    hgemm2p<0,1><<<PGRID, 256, SM128>>>(ah + 3L*MR*CC, al + 3L*MR*CC, Wh + 0*WC, rb, AA, 0);
    hgemm2p<0,1><<<PGRID, 256, SM128>>>(ah + 1L*MR*CC, al + 1L*MR*CC, Wh + 1*WC, kb, AA, 1);
    hgemm2p<0,0><<<PGRID, 256, SM128S>>>(ah + 2L*MR*CC, al, Wh + 2*WC, vb, AA, 2);
    // td + decay + scan
    hgemm_tanh_split<2,4><<<dim3(NTD/128, MR/64), 256, SM64>>>(ah, al, tdh, tdsh, tdsl);
    hgemm_decay<<<dim3(AA/128, MR/128), 256, SM128>>>(tdsh, tdsl, tdw2h, tdecay, wb);
    scan_kernel<<<BB*HH, 128>>>(kv_state, faaaa);
    // join gate, then groupnorm + out projection
    cudaStreamWaitEvent(0, eGate, 0);
    gn_gate_kernel<<<(MR*HH + 7)/8, 256>>>(ln_w, ln_b);
    hgemm2p<0,1><<<PGRID, 256, SM128>>>(gh, gl, Wh + 4*WC, out, CC, 4);
}